// round 8
// baseline (speedup 1.0000x reference)
#include <cuda_runtime.h>
#include <math.h>
#include <cstdint>

#define D_MODEL 768
#define NH      12
#define DHEAD   64
#define BATCH   8
#define SEQ     1024
#define TOK     (BATCH * SEQ)   // 8192

// Scratch (device globals — no runtime allocation allowed)
__device__ float g_q[TOK * D_MODEL];
__device__ float g_k[TOK * D_MODEL];
__device__ float g_v[TOK * D_MODEL];
__device__ float g_attn[TOK * D_MODEL];
__device__ float g_xr[TOK * D_MODEL];        // x rounded to tf32
__device__ float g_wqr[D_MODEL * D_MODEL];   // weights rounded to tf32
__device__ float g_wkr[D_MODEL * D_MODEL];
__device__ float g_wvr[D_MODEL * D_MODEL];
__device__ float g_wor[D_MODEL * D_MODEL];

__device__ __forceinline__ float to_tf32(float x) {
    float r;
    asm("cvt.rna.tf32.f32 %0, %1;" : "=f"(r) : "f"(x));
    return r;
}

__device__ __forceinline__ uint32_t smem_u32(const void* p) {
    uint32_t a;
    asm("{ .reg .u64 t; cvta.to.shared.u64 t, %1; cvt.u32.u64 %0, t; }"
        : "=r"(a) : "l"(p));
    return a;
}

// c += a @ b  (m16n8k8 tf32, fp32 accum)
__device__ __forceinline__ void mma_tf32(float* c, const float* a, float b0, float b1) {
    asm volatile(
        "mma.sync.aligned.m16n8k8.row.col.f32.tf32.tf32.f32 "
        "{%0,%1,%2,%3}, {%4,%5,%6,%7}, {%8,%9}, {%0,%1,%2,%3};"
        : "+f"(c[0]), "+f"(c[1]), "+f"(c[2]), "+f"(c[3])
        : "r"(__float_as_uint(a[0])), "r"(__float_as_uint(a[1])),
          "r"(__float_as_uint(a[2])), "r"(__float_as_uint(a[3])),
          "r"(__float_as_uint(b0)), "r"(__float_as_uint(b1)));
}

#define CP_ASYNC16(saddr, gptr) \
    asm volatile("cp.async.cg.shared.global [%0], [%1], 16;" \
                 :: "r"(saddr), "l"(gptr) : "memory")
#define CP_COMMIT() asm volatile("cp.async.commit_group;" ::: "memory")
#define CP_WAIT(n)  asm volatile("cp.async.wait_group %0;" :: "n"(n) : "memory")

// ===========================================================================
// Elementwise tf32 pre-rounding (float4 grid-stride)
// ===========================================================================
__global__ void __launch_bounds__(256)
round_tf32_kernel(const float* __restrict__ src, float* __restrict__ dst, int n4) {
    int i = blockIdx.x * blockDim.x + threadIdx.x;
    if (i < n4) {
        float4 v = ((const float4*)src)[i];
        v.x = to_tf32(v.x); v.y = to_tf32(v.y);
        v.z = to_tf32(v.z); v.w = to_tf32(v.w);
        ((float4*)dst)[i] = v;
    }
}

// ===========================================================================
// tf32 tensor-core GEMM + bias: C[M,N] = A[M,768] @ B(768,N) + bias[N]
// BMODE 0: B row-major [K, N]            (Wo)
// BMODE 1: B per-head stacked [H, D, DH]  (Wq/Wk/Wv)
// ROUND 1: round output to tf32 (downstream mma reads become lossless)
// A and B must be PRE-ROUNDED to tf32 (cp.async copies raw bytes; HW
// truncation of an already-rounded value is exact).
// 4-stage cp.async pipeline, BK=16, 128x128 tile, 256 threads.
// ===========================================================================
#define BK  16
#define NIT (D_MODEL / BK)   // 48
#define AS_STRIDE 20         // 80 B row pitch (16B-aligned), frag conflict-free
#define BS_STRIDE 136        // 544 B row pitch (16B-aligned), frag conflict-free
#define AS_SZ (128 * AS_STRIDE)
#define BS_SZ (BK * BS_STRIDE)
#define GSTAGES 4

template <int BMODE, int ROUND>
__global__ void __launch_bounds__(256)
mma_gemm_kernel(const float* __restrict__ A, const float* __restrict__ B,
                const float* __restrict__ bias, float* __restrict__ C) {
    extern __shared__ float gsm[];
    float* As_f = gsm;                         // [GSTAGES][128][AS_STRIDE]
    float* Bs_f = gsm + GSTAGES * AS_SZ;       // [GSTAGES][BK][BS_STRIDE]

    const int tid = threadIdx.x;
    const int lane = tid & 31;
    const int wid = tid >> 5;
    const int gid = lane >> 2;
    const int tig = lane & 3;
    const int warp_m = wid & 3;
    const int warp_n = wid >> 2;
    const int m0 = blockIdx.y * 128;
    const int n0 = blockIdx.x * 128;

    const uint32_t as_b = smem_u32(As_f);
    const uint32_t bs_b = smem_u32(Bs_f);

    // cp.async mapping: A tile 512 float4 (row=id>>2, col4=(id&3)*4),
    //                   B tile 512 float4 (krow=id>>5, col4=(id&31)*4)
    const int a_row0 = tid >> 2;
    const int a_col0 = (tid & 3) * 4;
    const int a_row1 = (tid + 256) >> 2;
    const int b_kr0 = tid >> 5;
    const int b_c0 = (tid & 31) * 4;
    const int b_kr1 = (tid + 256) >> 5;

#define LOAD_STAGE(k0, st)                                                    \
    do {                                                                      \
        CP_ASYNC16(as_b + ((st) * AS_SZ + a_row0 * AS_STRIDE + a_col0) * 4,   \
                   &A[(size_t)(m0 + a_row0) * D_MODEL + (k0) + a_col0]);      \
        CP_ASYNC16(as_b + ((st) * AS_SZ + a_row1 * AS_STRIDE + a_col0) * 4,   \
                   &A[(size_t)(m0 + a_row1) * D_MODEL + (k0) + a_col0]);      \
        if (BMODE == 0) {                                                     \
            CP_ASYNC16(bs_b + ((st) * BS_SZ + b_kr0 * BS_STRIDE + b_c0) * 4,  \
                       &B[(size_t)((k0) + b_kr0) * D_MODEL + n0 + b_c0]);     \
            CP_ASYNC16(bs_b + ((st) * BS_SZ + b_kr1 * BS_STRIDE + b_c0) * 4,  \
                       &B[(size_t)((k0) + b_kr1) * D_MODEL + n0 + b_c0]);     \
        } else {                                                              \
            const int c = n0 + b_c0;                                          \
            CP_ASYNC16(bs_b + ((st) * BS_SZ + b_kr0 * BS_STRIDE + b_c0) * 4,  \
                       &B[((size_t)(c >> 6) * D_MODEL + (k0) + b_kr0) * DHEAD + (c & 63)]); \
            CP_ASYNC16(bs_b + ((st) * BS_SZ + b_kr1 * BS_STRIDE + b_c0) * 4,  \
                       &B[((size_t)(c >> 6) * D_MODEL + (k0) + b_kr1) * DHEAD + (c & 63)]); \
        }                                                                     \
        CP_COMMIT();                                                          \
    } while (0)

    float acc[2][8][4];
#pragma unroll
    for (int mt = 0; mt < 2; mt++)
#pragma unroll
        for (int nt = 0; nt < 8; nt++)
#pragma unroll
            for (int i = 0; i < 4; i++) acc[mt][nt][i] = 0.0f;

    LOAD_STAGE(0, 0);
    LOAD_STAGE(BK, 1);
    LOAD_STAGE(2 * BK, 2);

#pragma unroll 1
    for (int it = 0; it < NIT; it++) {
        CP_WAIT(2);            // 3 groups always pending -> stage `it` complete
        __syncthreads();

        const float* Asr = As_f + (it & 3) * AS_SZ;
        const float* Bsr = Bs_f + (it & 3) * BS_SZ;

#pragma unroll
        for (int ks = 0; ks < 2; ks++) {
            const int kb = ks * 8;
            float a[2][4];
#pragma unroll
            for (int mt = 0; mt < 2; mt++) {
                const int r = warp_m * 32 + mt * 16 + gid;
                a[mt][0] = Asr[r * AS_STRIDE + kb + tig];
                a[mt][1] = Asr[(r + 8) * AS_STRIDE + kb + tig];
                a[mt][2] = Asr[r * AS_STRIDE + kb + tig + 4];
                a[mt][3] = Asr[(r + 8) * AS_STRIDE + kb + tig + 4];
            }
            float b[8][2];
#pragma unroll
            for (int nt = 0; nt < 8; nt++) {
                const int cn = warp_n * 64 + nt * 8 + gid;
                b[nt][0] = Bsr[(kb + tig) * BS_STRIDE + cn];
                b[nt][1] = Bsr[(kb + tig + 4) * BS_STRIDE + cn];
            }
#pragma unroll
            for (int mt = 0; mt < 2; mt++)
#pragma unroll
                for (int nt = 0; nt < 8; nt++)
                    mma_tf32(acc[mt][nt], a[mt], b[nt][0], b[nt][1]);
        }

        if (it + 3 < NIT) {
            LOAD_STAGE((it + 3) * BK, (it + 3) & 3);
        } else {
            CP_COMMIT();       // empty group keeps the pending count uniform
        }
    }

#pragma unroll
    for (int nt = 0; nt < 8; nt++) {
        const int cn = n0 + warp_n * 64 + nt * 8 + 2 * tig;
        const float2 bb = *(const float2*)&bias[cn];
#pragma unroll
        for (int mt = 0; mt < 2; mt++) {
            const int r = m0 + warp_m * 32 + mt * 16 + gid;
            float2 v0 = make_float2(acc[mt][nt][0] + bb.x, acc[mt][nt][1] + bb.y);
            float2 v1 = make_float2(acc[mt][nt][2] + bb.x, acc[mt][nt][3] + bb.y);
            if (ROUND) {
                v0.x = to_tf32(v0.x); v0.y = to_tf32(v0.y);
                v1.x = to_tf32(v1.x); v1.y = to_tf32(v1.y);
            }
            *(float2*)&C[(size_t)r * D_MODEL + cn] = v0;
            *(float2*)&C[(size_t)(r + 8) * D_MODEL + cn] = v1;
        }
    }
#undef LOAD_STAGE
}

// ===========================================================================
// Tensor-core flash attention (tf32 mma.sync).  (Unchanged from R6 except
// the output store is rounded to tf32 so the Wo GEMM cp.async path is
// lossless.)
// ===========================================================================
#define K_STRIDE 68
#define V_STRIDE 72
#define PS_STRIDE 76
#define KBUF     (64 * K_STRIDE)
#define VBUF     (64 * V_STRIDE)

__global__ void __launch_bounds__(256)
attention_kernel(const float* __restrict__ Q, const float* __restrict__ K,
                 const float* __restrict__ V, float* __restrict__ O) {
    extern __shared__ float smem[];
    float* Ks = smem;                    // [2][64][K_STRIDE]
    float* Vs = Ks + 2 * KBUF;           // [2][64][V_STRIDE]
    float* Ps = Vs + 2 * VBUF;           // [128][PS_STRIDE]  (also Q staging)

    const int tid = threadIdx.x;
    const int lane = tid & 31;
    const int wid = tid >> 5;
    const int gid = lane >> 2;
    const int tig = lane & 3;
    const int b = blockIdx.y / NH;
    const int h = blockIdx.y % NH;
    const size_t base = (size_t)b * SEQ * D_MODEL + (size_t)h * DHEAD;
    const int q0 = blockIdx.x * 128;

    const uint32_t smem_b = smem_u32(smem);
    const uint32_t ks_b = smem_b;
    const uint32_t vs_b = smem_b + 2 * KBUF * 4;
    const uint32_t ps_b = smem_b + (2 * KBUF + 2 * VBUF) * 4;

#pragma unroll
    for (int i = 0; i < 8; i++) {
        const int id = tid + i * 256;
        const int r = id >> 4, c4 = (id & 15) * 4;
        CP_ASYNC16(ps_b + (r * PS_STRIDE + c4) * 4,
                   Q + base + (size_t)(q0 + r) * D_MODEL + c4);
    }
    CP_COMMIT();

#define LOAD_KV(kt, buf)                                                      \
    do {                                                                      \
        _Pragma("unroll")                                                     \
        for (int i = 0; i < 4; i++) {                                         \
            const int id = tid + i * 256;                                     \
            const int r = id >> 4, c4 = (id & 15) * 4;                        \
            const size_t go = base + (size_t)((kt) * 64 + r) * D_MODEL + c4;  \
            CP_ASYNC16(ks_b + ((buf) * KBUF + r * K_STRIDE + c4) * 4, K + go); \
            CP_ASYNC16(vs_b + ((buf) * VBUF + r * V_STRIDE + c4) * 4, V + go); \
        }                                                                     \
        CP_COMMIT();                                                          \
    } while (0)

    LOAD_KV(0, 0);
    LOAD_KV(1, 1);

    CP_WAIT(2);
    __syncthreads();

    float qf[8][4];
    {
        const int r0 = (wid * 16 + gid) * PS_STRIDE;
        const int r1 = (wid * 16 + gid + 8) * PS_STRIDE;
#pragma unroll
        for (int kc = 0; kc < 8; kc++) {
            const int c = kc * 8 + tig;
            qf[kc][0] = to_tf32(0.125f * Ps[r0 + c]);
            qf[kc][1] = to_tf32(0.125f * Ps[r1 + c]);
            qf[kc][2] = to_tf32(0.125f * Ps[r0 + c + 4]);
            qf[kc][3] = to_tf32(0.125f * Ps[r1 + c + 4]);
        }
    }
    __syncthreads();

    float o_acc[8][4];
#pragma unroll
    for (int nt = 0; nt < 8; nt++)
#pragma unroll
        for (int i = 0; i < 4; i++) o_acc[nt][i] = 0.0f;
    float m0r = -1e30f, m1r = -1e30f, l0r = 0.0f, l1r = 0.0f;

    float* Pw = Ps + wid * 16 * PS_STRIDE;

#pragma unroll 1
    for (int kt = 0; kt < 16; kt++) {
        if (kt < 15) { CP_WAIT(1); } else { CP_WAIT(0); }
        __syncthreads();
        const float* KsC = Ks + (kt & 1) * KBUF;
        const float* VsC = Vs + (kt & 1) * VBUF;

        float s[8][4];
#pragma unroll
        for (int nt = 0; nt < 8; nt++)
#pragma unroll
            for (int i = 0; i < 4; i++) s[nt][i] = 0.0f;

#pragma unroll
        for (int kc = 0; kc < 8; kc++) {
            float bk0[8], bk1[8];
#pragma unroll
            for (int nt = 0; nt < 8; nt++) {
                const int jr = (nt * 8 + gid) * K_STRIDE + kc * 8 + tig;
                bk0[nt] = KsC[jr];
                bk1[nt] = KsC[jr + 4];
            }
#pragma unroll
            for (int nt = 0; nt < 8; nt++)
                mma_tf32(s[nt], qf[kc], bk0[nt], bk1[nt]);
        }

        float mx0 = s[0][0], mx1 = s[0][2];
#pragma unroll
        for (int nt = 0; nt < 8; nt++) {
            mx0 = fmaxf(mx0, fmaxf(s[nt][0], s[nt][1]));
            mx1 = fmaxf(mx1, fmaxf(s[nt][2], s[nt][3]));
        }
        mx0 = fmaxf(mx0, __shfl_xor_sync(0xffffffffu, mx0, 1));
        mx0 = fmaxf(mx0, __shfl_xor_sync(0xffffffffu, mx0, 2));
        mx1 = fmaxf(mx1, __shfl_xor_sync(0xffffffffu, mx1, 1));
        mx1 = fmaxf(mx1, __shfl_xor_sync(0xffffffffu, mx1, 2));

        const float nm0 = fmaxf(m0r, mx0);
        const float nm1 = fmaxf(m1r, mx1);
        const float fac0 = __expf(m0r - nm0);
        const float fac1 = __expf(m1r - nm1);
        m0r = nm0; m1r = nm1;

        float sum0 = 0.0f, sum1 = 0.0f;
#pragma unroll
        for (int nt = 0; nt < 8; nt++) {
            s[nt][0] = __expf(s[nt][0] - nm0);
            s[nt][1] = __expf(s[nt][1] - nm0);
            s[nt][2] = __expf(s[nt][2] - nm1);
            s[nt][3] = __expf(s[nt][3] - nm1);
            sum0 += s[nt][0] + s[nt][1];
            sum1 += s[nt][2] + s[nt][3];
        }
        sum0 += __shfl_xor_sync(0xffffffffu, sum0, 1);
        sum0 += __shfl_xor_sync(0xffffffffu, sum0, 2);
        sum1 += __shfl_xor_sync(0xffffffffu, sum1, 1);
        sum1 += __shfl_xor_sync(0xffffffffu, sum1, 2);
        l0r = l0r * fac0 + sum0;
        l1r = l1r * fac1 + sum1;

#pragma unroll
        for (int nt = 0; nt < 8; nt++) {
            o_acc[nt][0] *= fac0; o_acc[nt][1] *= fac0;
            o_acc[nt][2] *= fac1; o_acc[nt][3] *= fac1;
        }

#pragma unroll
        for (int nt = 0; nt < 8; nt++) {
            const int c = nt * 8 + 2 * tig;
            *(float2*)&Pw[gid * PS_STRIDE + c] =
                make_float2(to_tf32(s[nt][0]), to_tf32(s[nt][1]));
            *(float2*)&Pw[(gid + 8) * PS_STRIDE + c] =
                make_float2(to_tf32(s[nt][2]), to_tf32(s[nt][3]));
        }
        __syncwarp();

#pragma unroll
        for (int kc = 0; kc < 8; kc++) {
            float pa[4];
            const int c = kc * 8 + tig;
            pa[0] = Pw[gid * PS_STRIDE + c];
            pa[1] = Pw[(gid + 8) * PS_STRIDE + c];
            pa[2] = Pw[gid * PS_STRIDE + c + 4];
            pa[3] = Pw[(gid + 8) * PS_STRIDE + c + 4];
            float bv0[8], bv1[8];
            const int vr0 = (kc * 8 + tig) * V_STRIDE;
            const int vr1 = (kc * 8 + tig + 4) * V_STRIDE;
#pragma unroll
            for (int nt = 0; nt < 8; nt++) {
                bv0[nt] = VsC[vr0 + nt * 8 + gid];
                bv1[nt] = VsC[vr1 + nt * 8 + gid];
            }
#pragma unroll
            for (int nt = 0; nt < 8; nt++)
                mma_tf32(o_acc[nt], pa, bv0[nt], bv1[nt]);
        }

        __syncthreads();
        if (kt + 2 < 16) LOAD_KV(kt + 2, kt & 1);
    }

    const float inv0 = 1.0f / l0r;
    const float inv1 = 1.0f / l1r;
    const int r0 = q0 + wid * 16 + gid;
#pragma unroll
    for (int nt = 0; nt < 8; nt++) {
        const int c = nt * 8 + 2 * tig;
        *(float2*)&O[base + (size_t)r0 * D_MODEL + c] =
            make_float2(to_tf32(o_acc[nt][0] * inv0), to_tf32(o_acc[nt][1] * inv0));
        *(float2*)&O[base + (size_t)(r0 + 8) * D_MODEL + c] =
            make_float2(to_tf32(o_acc[nt][2] * inv1), to_tf32(o_acc[nt][3] * inv1));
    }
#undef LOAD_KV
}

// ---------------------------------------------------------------------------
extern "C" void kernel_launch(void* const* d_in, const int* in_sizes, int n_in,
                              void* d_out, int out_size) {
    (void)in_sizes; (void)n_in; (void)out_size;
    const float* x  = (const float*)d_in[0];
    const float* Wq = (const float*)d_in[1];
    const float* bq = (const float*)d_in[2];
    const float* Wk = (const float*)d_in[3];
    const float* bk = (const float*)d_in[4];
    const float* Wv = (const float*)d_in[5];
    const float* bv = (const float*)d_in[6];
    const float* Wo = (const float*)d_in[7];
    const float* bo = (const float*)d_in[8];
    float* out = (float*)d_out;

    float *q, *k, *v, *attn, *xr, *wqr, *wkr, *wvr, *wor;
    cudaGetSymbolAddress((void**)&q, g_q);
    cudaGetSymbolAddress((void**)&k, g_k);
    cudaGetSymbolAddress((void**)&v, g_v);
    cudaGetSymbolAddress((void**)&attn, g_attn);
    cudaGetSymbolAddress((void**)&xr, g_xr);
    cudaGetSymbolAddress((void**)&wqr, g_wqr);
    cudaGetSymbolAddress((void**)&wkr, g_wkr);
    cudaGetSymbolAddress((void**)&wvr, g_wvr);
    cudaGetSymbolAddress((void**)&wor, g_wor);

    const int smem_gemm = GSTAGES * (AS_SZ + BS_SZ) * (int)sizeof(float); // 75776
    cudaFuncSetAttribute(mma_gemm_kernel<0, 0>,
                         cudaFuncAttributeMaxDynamicSharedMemorySize, smem_gemm);
    cudaFuncSetAttribute(mma_gemm_kernel<1, 1>,
                         cudaFuncAttributeMaxDynamicSharedMemorySize, smem_gemm);
    const int smem_attn =
        (2 * KBUF + 2 * VBUF + 128 * PS_STRIDE) * (int)sizeof(float); // 110592
    cudaFuncSetAttribute(attention_kernel,
                         cudaFuncAttributeMaxDynamicSharedMemorySize, smem_attn);

    // --- pre-round x and weights to tf32 (makes cp.async raw copies exact) ---
    const int xn4 = TOK * D_MODEL / 4;        // 1572864
    const int wn4 = D_MODEL * D_MODEL / 4;    // 147456
    round_tf32_kernel<<<(xn4 + 255) / 256, 256>>>(x, xr, xn4);
    round_tf32_kernel<<<(wn4 + 255) / 256, 256>>>(Wq, wqr, wn4);
    round_tf32_kernel<<<(wn4 + 255) / 256, 256>>>(Wk, wkr, wn4);
    round_tf32_kernel<<<(wn4 + 255) / 256, 256>>>(Wv, wvr, wn4);
    round_tf32_kernel<<<(wn4 + 255) / 256, 256>>>(Wo, wor, wn4);

    // QKV projections (outputs rounded to tf32 for the attention mma path)
    dim3 gemm_grid(D_MODEL / 128, TOK / 128);   // (6, 64)
    mma_gemm_kernel<1, 1><<<gemm_grid, 256, smem_gemm>>>(xr, wqr, bq, q);
    mma_gemm_kernel<1, 1><<<gemm_grid, 256, smem_gemm>>>(xr, wkr, bk, k);
    mma_gemm_kernel<1, 1><<<gemm_grid, 256, smem_gemm>>>(xr, wvr, bv, v);

    // Tensor-core flash attention
    dim3 attn_grid(SEQ / 128, BATCH * NH);      // (8, 96)
    attention_kernel<<<attn_grid, 256, smem_attn>>>(q, k, v, attn);

    // Output projection (full fp32 output)
    mma_gemm_kernel<0, 0><<<gemm_grid, 256, smem_gemm>>>(attn, wor, bo, out);
}

// round 9
// speedup vs baseline: 1.4977x; 1.4977x over previous
#include <cuda_runtime.h>
#include <math.h>
#include <cstdint>

#define D_MODEL 768
#define NH      12
#define DHEAD   64
#define BATCH   8
#define SEQ     1024
#define TOK     (BATCH * SEQ)   // 8192

// Scratch (device globals — no runtime allocation allowed)
__device__ float g_q[TOK * D_MODEL];
__device__ float g_k[TOK * D_MODEL];
__device__ float g_v[TOK * D_MODEL];
__device__ float g_attn[TOK * D_MODEL];

__device__ __forceinline__ float to_tf32(float x) {
    float r;
    asm("cvt.rna.tf32.f32 %0, %1;" : "=f"(r) : "f"(x));
    return r;
}

__device__ __forceinline__ uint32_t smem_u32(const void* p) {
    uint32_t a;
    asm("{ .reg .u64 t; cvta.to.shared.u64 t, %1; cvt.u32.u64 %0, t; }"
        : "=r"(a) : "l"(p));
    return a;
}

// c += a @ b  (m16n8k8 tf32, fp32 accum)
__device__ __forceinline__ void mma_tf32(float* c, const float* a, float b0, float b1) {
    asm volatile(
        "mma.sync.aligned.m16n8k8.row.col.f32.tf32.tf32.f32 "
        "{%0,%1,%2,%3}, {%4,%5,%6,%7}, {%8,%9}, {%0,%1,%2,%3};"
        : "+f"(c[0]), "+f"(c[1]), "+f"(c[2]), "+f"(c[3])
        : "r"(__float_as_uint(a[0])), "r"(__float_as_uint(a[1])),
          "r"(__float_as_uint(a[2])), "r"(__float_as_uint(a[3])),
          "r"(__float_as_uint(b0)), "r"(__float_as_uint(b1)));
}

#define CP_ASYNC16(saddr, gptr) \
    asm volatile("cp.async.cg.shared.global [%0], [%1], 16;" \
                 :: "r"(saddr), "l"(gptr) : "memory")
#define CP_COMMIT() asm volatile("cp.async.commit_group;" ::: "memory")
#define CP_WAIT(n)  asm volatile("cp.async.wait_group %0;" :: "n"(n) : "memory")

// ===========================================================================
// tf32 tensor-core GEMM + bias: C[M,N] = A[M,768] @ B(768,N) + bias[N]
// BMODE 0: B row-major [K, N]            (Wo)
// BMODE 1: B per-head stacked [H, D, DH]  (Wq/Wk/Wv)
// ROUND 1: round output to tf32 (so downstream mma reads are lossless)
// CTA tile 128x128, BK=32, 256 threads (8 warps, 4x2), warp tile 32x64.
// Double-buffered smem, register-staged global loads (R6 structure).
// ===========================================================================
#define BK  32
#define NIT (D_MODEL / BK)   // 24
#define AS_STRIDE 36         // 32 cols + 4 pad (frag banks (4*gid+tig)%32 distinct)
#define BS_STRIDE 136        // 128 cols + 8 pad (frag banks 8*tig+gid distinct)
#define AS_SZ (128 * AS_STRIDE)
#define BS_SZ (BK * BS_STRIDE)

template <int BMODE, int ROUND>
__global__ void __launch_bounds__(256)
mma_gemm_kernel(const float* __restrict__ A, const float* __restrict__ B,
                const float* __restrict__ bias, float* __restrict__ C) {
    extern __shared__ float gsm[];
    float* As_f = gsm;                 // [2][128][AS_STRIDE]
    float* Bs_f = gsm + 2 * AS_SZ;     // [2][BK][BS_STRIDE]

    const int tid = threadIdx.x;
    const int lane = tid & 31;
    const int wid = tid >> 5;
    const int gid = lane >> 2;
    const int tig = lane & 3;
    const int warp_m = wid & 3;
    const int warp_n = wid >> 2;
    const int m0 = blockIdx.y * 128;
    const int n0 = blockIdx.x * 128;

    // A tile: 128x32 floats = 1024 float4, 4 per thread: row=id>>3, col4=(id&7)*4
    // B tile: 32x128 floats = 1024 float4, 4 per thread: krow=id>>5, col4=(id&31)*4
    int a_row[4], b_kr[4];
    const int a_col = (tid & 7) * 4;
    const int b_c   = (tid & 31) * 4;
#pragma unroll
    for (int i = 0; i < 4; i++) {
        a_row[i] = (tid + i * 256) >> 3;
        b_kr[i]  = (tid + i * 256) >> 5;
    }

    float acc[2][8][4];
#pragma unroll
    for (int mt = 0; mt < 2; mt++)
#pragma unroll
        for (int nt = 0; nt < 8; nt++)
#pragma unroll
            for (int i = 0; i < 4; i++) acc[mt][nt][i] = 0.0f;

    float4 ra[4], rb[4];

#define LDG_TILE(k0)                                                          \
    do {                                                                      \
        _Pragma("unroll")                                                     \
        for (int i = 0; i < 4; i++)                                           \
            ra[i] = *(const float4*)&A[(size_t)(m0 + a_row[i]) * D_MODEL + (k0) + a_col]; \
        if (BMODE == 0) {                                                     \
            _Pragma("unroll")                                                 \
            for (int i = 0; i < 4; i++)                                       \
                rb[i] = *(const float4*)&B[(size_t)((k0) + b_kr[i]) * D_MODEL + n0 + b_c]; \
        } else {                                                              \
            const int c = n0 + b_c;                                           \
            _Pragma("unroll")                                                 \
            for (int i = 0; i < 4; i++)                                       \
                rb[i] = *(const float4*)&B[((size_t)(c >> 6) * D_MODEL + (k0) + b_kr[i]) * DHEAD + (c & 63)]; \
        }                                                                     \
    } while (0)

#define STS_TILE(buf)                                                         \
    do {                                                                      \
        _Pragma("unroll")                                                     \
        for (int i = 0; i < 4; i++) {                                         \
            float4 t;                                                         \
            t.x = to_tf32(ra[i].x); t.y = to_tf32(ra[i].y);                   \
            t.z = to_tf32(ra[i].z); t.w = to_tf32(ra[i].w);                   \
            *(float4*)&As_f[(buf) * AS_SZ + a_row[i] * AS_STRIDE + a_col] = t; \
            t.x = to_tf32(rb[i].x); t.y = to_tf32(rb[i].y);                   \
            t.z = to_tf32(rb[i].z); t.w = to_tf32(rb[i].w);                   \
            *(float4*)&Bs_f[(buf) * BS_SZ + b_kr[i] * BS_STRIDE + b_c] = t;   \
        }                                                                     \
    } while (0)

    // prologue: tile 0 -> buf 0
    LDG_TILE(0);
    STS_TILE(0);
    __syncthreads();

#pragma unroll 1
    for (int it = 0; it < NIT; it++) {
        const int buf = it & 1;
        if (it + 1 < NIT) LDG_TILE((it + 1) * BK);

        const float* Asr = As_f + buf * AS_SZ;
        const float* Bsr = Bs_f + buf * BS_SZ;

        // compute 4 k-steps of 8 from smem buf
#pragma unroll
        for (int ks = 0; ks < 4; ks++) {
            const int kb = ks * 8;
            float a[2][4];
#pragma unroll
            for (int mt = 0; mt < 2; mt++) {
                const int r = warp_m * 32 + mt * 16 + gid;
                a[mt][0] = Asr[r * AS_STRIDE + kb + tig];
                a[mt][1] = Asr[(r + 8) * AS_STRIDE + kb + tig];
                a[mt][2] = Asr[r * AS_STRIDE + kb + tig + 4];
                a[mt][3] = Asr[(r + 8) * AS_STRIDE + kb + tig + 4];
            }
            float b[8][2];
#pragma unroll
            for (int nt = 0; nt < 8; nt++) {
                const int cn = warp_n * 64 + nt * 8 + gid;
                b[nt][0] = Bsr[(kb + tig) * BS_STRIDE + cn];
                b[nt][1] = Bsr[(kb + tig + 4) * BS_STRIDE + cn];
            }
#pragma unroll
            for (int mt = 0; mt < 2; mt++)
#pragma unroll
                for (int nt = 0; nt < 8; nt++)
                    mma_tf32(acc[mt][nt], a[mt], b[nt][0], b[nt][1]);
        }

        if (it + 1 < NIT) {
            __syncthreads();       // everyone done reading buf^1 from prev iter
            STS_TILE(buf ^ 1);
            __syncthreads();
        }
    }

    // ---- epilogue: fragment-direct stores + bias ----
#pragma unroll
    for (int nt = 0; nt < 8; nt++) {
        const int cn = n0 + warp_n * 64 + nt * 8 + 2 * tig;
        const float2 bb = *(const float2*)&bias[cn];
#pragma unroll
        for (int mt = 0; mt < 2; mt++) {
            const int r = m0 + warp_m * 32 + mt * 16 + gid;
            float2 v0 = make_float2(acc[mt][nt][0] + bb.x, acc[mt][nt][1] + bb.y);
            float2 v1 = make_float2(acc[mt][nt][2] + bb.x, acc[mt][nt][3] + bb.y);
            if (ROUND) {
                v0.x = to_tf32(v0.x); v0.y = to_tf32(v0.y);
                v1.x = to_tf32(v1.x); v1.y = to_tf32(v1.y);
            }
            *(float2*)&C[(size_t)r * D_MODEL + cn] = v0;
            *(float2*)&C[(size_t)(r + 8) * D_MODEL + cn] = v1;
        }
    }
#undef LDG_TILE
#undef STS_TILE
}

// ===========================================================================
// Tensor-core flash attention (tf32 mma.sync). UNCHANGED from the passing
// R6 version (234 us).
// ===========================================================================
#define K_STRIDE 68
#define V_STRIDE 72
#define PS_STRIDE 76
#define KBUF     (64 * K_STRIDE)
#define VBUF     (64 * V_STRIDE)

__global__ void __launch_bounds__(256)
attention_kernel(const float* __restrict__ Q, const float* __restrict__ K,
                 const float* __restrict__ V, float* __restrict__ O) {
    extern __shared__ float smem[];
    float* Ks = smem;                    // [2][64][K_STRIDE]
    float* Vs = Ks + 2 * KBUF;           // [2][64][V_STRIDE]
    float* Ps = Vs + 2 * VBUF;           // [128][PS_STRIDE]  (also Q staging)

    const int tid = threadIdx.x;
    const int lane = tid & 31;
    const int wid = tid >> 5;
    const int gid = lane >> 2;
    const int tig = lane & 3;
    const int b = blockIdx.y / NH;
    const int h = blockIdx.y % NH;
    const size_t base = (size_t)b * SEQ * D_MODEL + (size_t)h * DHEAD;
    const int q0 = blockIdx.x * 128;

    const uint32_t smem_b = smem_u32(smem);
    const uint32_t ks_b = smem_b;
    const uint32_t vs_b = smem_b + 2 * KBUF * 4;
    const uint32_t ps_b = smem_b + (2 * KBUF + 2 * VBUF) * 4;

#pragma unroll
    for (int i = 0; i < 8; i++) {
        const int id = tid + i * 256;
        const int r = id >> 4, c4 = (id & 15) * 4;
        CP_ASYNC16(ps_b + (r * PS_STRIDE + c4) * 4,
                   Q + base + (size_t)(q0 + r) * D_MODEL + c4);
    }
    CP_COMMIT();

#define LOAD_KV(kt, buf)                                                      \
    do {                                                                      \
        _Pragma("unroll")                                                     \
        for (int i = 0; i < 4; i++) {                                         \
            const int id = tid + i * 256;                                     \
            const int r = id >> 4, c4 = (id & 15) * 4;                        \
            const size_t go = base + (size_t)((kt) * 64 + r) * D_MODEL + c4;  \
            CP_ASYNC16(ks_b + ((buf) * KBUF + r * K_STRIDE + c4) * 4, K + go); \
            CP_ASYNC16(vs_b + ((buf) * VBUF + r * V_STRIDE + c4) * 4, V + go); \
        }                                                                     \
        CP_COMMIT();                                                          \
    } while (0)

    LOAD_KV(0, 0);
    LOAD_KV(1, 1);

    CP_WAIT(2);
    __syncthreads();

    float qf[8][4];
    {
        const int r0 = (wid * 16 + gid) * PS_STRIDE;
        const int r1 = (wid * 16 + gid + 8) * PS_STRIDE;
#pragma unroll
        for (int kc = 0; kc < 8; kc++) {
            const int c = kc * 8 + tig;
            qf[kc][0] = to_tf32(0.125f * Ps[r0 + c]);
            qf[kc][1] = to_tf32(0.125f * Ps[r1 + c]);
            qf[kc][2] = to_tf32(0.125f * Ps[r0 + c + 4]);
            qf[kc][3] = to_tf32(0.125f * Ps[r1 + c + 4]);
        }
    }
    __syncthreads();

    float o_acc[8][4];
#pragma unroll
    for (int nt = 0; nt < 8; nt++)
#pragma unroll
        for (int i = 0; i < 4; i++) o_acc[nt][i] = 0.0f;
    float m0r = -1e30f, m1r = -1e30f, l0r = 0.0f, l1r = 0.0f;

    float* Pw = Ps + wid * 16 * PS_STRIDE;

#pragma unroll 1
    for (int kt = 0; kt < 16; kt++) {
        if (kt < 15) { CP_WAIT(1); } else { CP_WAIT(0); }
        __syncthreads();
        const float* KsC = Ks + (kt & 1) * KBUF;
        const float* VsC = Vs + (kt & 1) * VBUF;

        float s[8][4];
#pragma unroll
        for (int nt = 0; nt < 8; nt++)
#pragma unroll
            for (int i = 0; i < 4; i++) s[nt][i] = 0.0f;

#pragma unroll
        for (int kc = 0; kc < 8; kc++) {
            float bk0[8], bk1[8];
#pragma unroll
            for (int nt = 0; nt < 8; nt++) {
                const int jr = (nt * 8 + gid) * K_STRIDE + kc * 8 + tig;
                bk0[nt] = KsC[jr];
                bk1[nt] = KsC[jr + 4];
            }
#pragma unroll
            for (int nt = 0; nt < 8; nt++)
                mma_tf32(s[nt], qf[kc], bk0[nt], bk1[nt]);
        }

        float mx0 = s[0][0], mx1 = s[0][2];
#pragma unroll
        for (int nt = 0; nt < 8; nt++) {
            mx0 = fmaxf(mx0, fmaxf(s[nt][0], s[nt][1]));
            mx1 = fmaxf(mx1, fmaxf(s[nt][2], s[nt][3]));
        }
        mx0 = fmaxf(mx0, __shfl_xor_sync(0xffffffffu, mx0, 1));
        mx0 = fmaxf(mx0, __shfl_xor_sync(0xffffffffu, mx0, 2));
        mx1 = fmaxf(mx1, __shfl_xor_sync(0xffffffffu, mx1, 1));
        mx1 = fmaxf(mx1, __shfl_xor_sync(0xffffffffu, mx1, 2));

        const float nm0 = fmaxf(m0r, mx0);
        const float nm1 = fmaxf(m1r, mx1);
        const float fac0 = __expf(m0r - nm0);
        const float fac1 = __expf(m1r - nm1);
        m0r = nm0; m1r = nm1;

        float sum0 = 0.0f, sum1 = 0.0f;
#pragma unroll
        for (int nt = 0; nt < 8; nt++) {
            s[nt][0] = __expf(s[nt][0] - nm0);
            s[nt][1] = __expf(s[nt][1] - nm0);
            s[nt][2] = __expf(s[nt][2] - nm1);
            s[nt][3] = __expf(s[nt][3] - nm1);
            sum0 += s[nt][0] + s[nt][1];
            sum1 += s[nt][2] + s[nt][3];
        }
        sum0 += __shfl_xor_sync(0xffffffffu, sum0, 1);
        sum0 += __shfl_xor_sync(0xffffffffu, sum0, 2);
        sum1 += __shfl_xor_sync(0xffffffffu, sum1, 1);
        sum1 += __shfl_xor_sync(0xffffffffu, sum1, 2);
        l0r = l0r * fac0 + sum0;
        l1r = l1r * fac1 + sum1;

#pragma unroll
        for (int nt = 0; nt < 8; nt++) {
            o_acc[nt][0] *= fac0; o_acc[nt][1] *= fac0;
            o_acc[nt][2] *= fac1; o_acc[nt][3] *= fac1;
        }

#pragma unroll
        for (int nt = 0; nt < 8; nt++) {
            const int c = nt * 8 + 2 * tig;
            *(float2*)&Pw[gid * PS_STRIDE + c] =
                make_float2(to_tf32(s[nt][0]), to_tf32(s[nt][1]));
            *(float2*)&Pw[(gid + 8) * PS_STRIDE + c] =
                make_float2(to_tf32(s[nt][2]), to_tf32(s[nt][3]));
        }
        __syncwarp();

#pragma unroll
        for (int kc = 0; kc < 8; kc++) {
            float pa[4];
            const int c = kc * 8 + tig;
            pa[0] = Pw[gid * PS_STRIDE + c];
            pa[1] = Pw[(gid + 8) * PS_STRIDE + c];
            pa[2] = Pw[gid * PS_STRIDE + c + 4];
            pa[3] = Pw[(gid + 8) * PS_STRIDE + c + 4];
            float bv0[8], bv1[8];
            const int vr0 = (kc * 8 + tig) * V_STRIDE;
            const int vr1 = (kc * 8 + tig + 4) * V_STRIDE;
#pragma unroll
            for (int nt = 0; nt < 8; nt++) {
                bv0[nt] = VsC[vr0 + nt * 8 + gid];
                bv1[nt] = VsC[vr1 + nt * 8 + gid];
            }
#pragma unroll
            for (int nt = 0; nt < 8; nt++)
                mma_tf32(o_acc[nt], pa, bv0[nt], bv1[nt]);
        }

        __syncthreads();
        if (kt + 2 < 16) LOAD_KV(kt + 2, kt & 1);
    }

    const float inv0 = 1.0f / l0r;
    const float inv1 = 1.0f / l1r;
    const int r0 = q0 + wid * 16 + gid;
#pragma unroll
    for (int nt = 0; nt < 8; nt++) {
        const int c = nt * 8 + 2 * tig;
        *(float2*)&O[base + (size_t)r0 * D_MODEL + c] =
            make_float2(o_acc[nt][0] * inv0, o_acc[nt][1] * inv0);
        *(float2*)&O[base + (size_t)(r0 + 8) * D_MODEL + c] =
            make_float2(o_acc[nt][2] * inv1, o_acc[nt][3] * inv1);
    }
#undef LOAD_KV
}

// ---------------------------------------------------------------------------
extern "C" void kernel_launch(void* const* d_in, const int* in_sizes, int n_in,
                              void* d_out, int out_size) {
    (void)in_sizes; (void)n_in; (void)out_size;
    const float* x  = (const float*)d_in[0];
    const float* Wq = (const float*)d_in[1];
    const float* bq = (const float*)d_in[2];
    const float* Wk = (const float*)d_in[3];
    const float* bk = (const float*)d_in[4];
    const float* Wv = (const float*)d_in[5];
    const float* bv = (const float*)d_in[6];
    const float* Wo = (const float*)d_in[7];
    const float* bo = (const float*)d_in[8];
    float* out = (float*)d_out;

    float *q, *k, *v, *attn;
    cudaGetSymbolAddress((void**)&q, g_q);
    cudaGetSymbolAddress((void**)&k, g_k);
    cudaGetSymbolAddress((void**)&v, g_v);
    cudaGetSymbolAddress((void**)&attn, g_attn);

    const int smem_gemm = 2 * (AS_SZ + BS_SZ) * (int)sizeof(float); // 71680
    cudaFuncSetAttribute(mma_gemm_kernel<0, 0>,
                         cudaFuncAttributeMaxDynamicSharedMemorySize, smem_gemm);
    cudaFuncSetAttribute(mma_gemm_kernel<1, 1>,
                         cudaFuncAttributeMaxDynamicSharedMemorySize, smem_gemm);
    const int smem_attn =
        (2 * KBUF + 2 * VBUF + 128 * PS_STRIDE) * (int)sizeof(float); // 110592
    cudaFuncSetAttribute(attention_kernel,
                         cudaFuncAttributeMaxDynamicSharedMemorySize, smem_attn);

    // QKV projections (outputs rounded to tf32 for the attention mma path)
    dim3 gemm_grid(D_MODEL / 128, TOK / 128);   // (6, 64)
    mma_gemm_kernel<1, 1><<<gemm_grid, 256, smem_gemm>>>(x, Wq, bq, q);
    mma_gemm_kernel<1, 1><<<gemm_grid, 256, smem_gemm>>>(x, Wk, bk, k);
    mma_gemm_kernel<1, 1><<<gemm_grid, 256, smem_gemm>>>(x, Wv, bv, v);

    // Tensor-core flash attention
    dim3 attn_grid(SEQ / 128, BATCH * NH);      // (8, 96)
    attention_kernel<<<attn_grid, 256, smem_attn>>>(q, k, v, attn);

    // Output projection (full fp32 output)
    mma_gemm_kernel<0, 0><<<gemm_grid, 256, smem_gemm>>>(attn, Wo, bo, out);
}

// round 11
// speedup vs baseline: 1.6833x; 1.1239x over previous
#include <cuda_runtime.h>
#include <math.h>
#include <cstdint>

#define D_MODEL 768
#define NH      12
#define DHEAD   64
#define BATCH   8
#define SEQ     1024
#define TOK     (BATCH * SEQ)   // 8192

// Scratch (device globals — no runtime allocation allowed)
__device__ float g_q[TOK * D_MODEL];
__device__ float g_k[TOK * D_MODEL];
__device__ float g_v[TOK * D_MODEL];
__device__ float g_attn[TOK * D_MODEL];

__device__ __forceinline__ float to_tf32(float x) {
    float r;
    asm("cvt.rna.tf32.f32 %0, %1;" : "=f"(r) : "f"(x));
    return r;
}

__device__ __forceinline__ uint32_t smem_u32(const void* p) {
    uint32_t a;
    asm("{ .reg .u64 t; cvta.to.shared.u64 t, %1; cvt.u32.u64 %0, t; }"
        : "=r"(a) : "l"(p));
    return a;
}

// c += a @ b  (m16n8k8 tf32, fp32 accum)
__device__ __forceinline__ void mma_tf32(float* c, const float* a, float b0, float b1) {
    asm volatile(
        "mma.sync.aligned.m16n8k8.row.col.f32.tf32.tf32.f32 "
        "{%0,%1,%2,%3}, {%4,%5,%6,%7}, {%8,%9}, {%0,%1,%2,%3};"
        : "+f"(c[0]), "+f"(c[1]), "+f"(c[2]), "+f"(c[3])
        : "r"(__float_as_uint(a[0])), "r"(__float_as_uint(a[1])),
          "r"(__float_as_uint(a[2])), "r"(__float_as_uint(a[3])),
          "r"(__float_as_uint(b0)), "r"(__float_as_uint(b1)));
}

#define CP_ASYNC16(saddr, gptr) \
    asm volatile("cp.async.cg.shared.global [%0], [%1], 16;" \
                 :: "r"(saddr), "l"(gptr) : "memory")
#define CP_COMMIT() asm volatile("cp.async.commit_group;" ::: "memory")
#define CP_WAIT(n)  asm volatile("cp.async.wait_group %0;" :: "n"(n) : "memory")

// ===========================================================================
// tf32 tensor-core GEMM + bias.  CTA tile 128x128, BK=32, 256 threads,
// warp tile 32x64, double-buffered smem, register-staged global loads,
// ONE __syncthreads per mainloop iteration (STS after compute).
// QKV=1: fused Q/K/V projection, blockIdx.z selects weights/bias/output,
//        B is per-head stacked [H, D, DH], output rounded to tf32.
// QKV=0: single GEMM, B row-major [K,N], full fp32 output (Wo).
// ===========================================================================
#define BK  32
#define NIT (D_MODEL / BK)   // 24
#define AS_STRIDE 36
#define BS_STRIDE 136
#define AS_SZ (128 * AS_STRIDE)
#define BS_SZ (BK * BS_STRIDE)

template <int QKV>
__global__ void __launch_bounds__(256, 2)
mma_gemm_kernel(const float* __restrict__ A,
                const float* __restrict__ B0, const float* __restrict__ bias0,
                float* __restrict__ C0,
                const float* __restrict__ B1, const float* __restrict__ bias1,
                float* __restrict__ C1,
                const float* __restrict__ B2, const float* __restrict__ bias2,
                float* __restrict__ C2) {
    extern __shared__ float gsm[];
    float* As_f = gsm;                 // [2][128][AS_STRIDE]
    float* Bs_f = gsm + 2 * AS_SZ;     // [2][BK][BS_STRIDE]

    const float* B    = B0;
    const float* bias = bias0;
    float*       C    = C0;
    if (QKV) {
        if (blockIdx.z == 1) { B = B1; bias = bias1; C = C1; }
        else if (blockIdx.z == 2) { B = B2; bias = bias2; C = C2; }
    }

    const int tid = threadIdx.x;
    const int lane = tid & 31;
    const int wid = tid >> 5;
    const int gid = lane >> 2;
    const int tig = lane & 3;
    const int warp_m = wid & 3;
    const int warp_n = wid >> 2;
    const int m0 = blockIdx.y * 128;
    const int n0 = blockIdx.x * 128;

    int a_row[4], b_kr[4];
    const int a_col = (tid & 7) * 4;
    const int b_c   = (tid & 31) * 4;
#pragma unroll
    for (int i = 0; i < 4; i++) {
        a_row[i] = (tid + i * 256) >> 3;
        b_kr[i]  = (tid + i * 256) >> 5;
    }

    float acc[2][8][4];
#pragma unroll
    for (int mt = 0; mt < 2; mt++)
#pragma unroll
        for (int nt = 0; nt < 8; nt++)
#pragma unroll
            for (int i = 0; i < 4; i++) acc[mt][nt][i] = 0.0f;

    float4 ra[4], rb[4];

#define LDG_TILE(k0)                                                          \
    do {                                                                      \
        _Pragma("unroll")                                                     \
        for (int i = 0; i < 4; i++)                                           \
            ra[i] = *(const float4*)&A[(size_t)(m0 + a_row[i]) * D_MODEL + (k0) + a_col]; \
        if (QKV == 0) {                                                       \
            _Pragma("unroll")                                                 \
            for (int i = 0; i < 4; i++)                                       \
                rb[i] = *(const float4*)&B[(size_t)((k0) + b_kr[i]) * D_MODEL + n0 + b_c]; \
        } else {                                                              \
            const int c = n0 + b_c;                                           \
            _Pragma("unroll")                                                 \
            for (int i = 0; i < 4; i++)                                       \
                rb[i] = *(const float4*)&B[((size_t)(c >> 6) * D_MODEL + (k0) + b_kr[i]) * DHEAD + (c & 63)]; \
        }                                                                     \
    } while (0)

#define STS_TILE(buf)                                                         \
    do {                                                                      \
        _Pragma("unroll")                                                     \
        for (int i = 0; i < 4; i++) {                                         \
            float4 t;                                                         \
            t.x = to_tf32(ra[i].x); t.y = to_tf32(ra[i].y);                   \
            t.z = to_tf32(ra[i].z); t.w = to_tf32(ra[i].w);                   \
            *(float4*)&As_f[(buf) * AS_SZ + a_row[i] * AS_STRIDE + a_col] = t; \
            t.x = to_tf32(rb[i].x); t.y = to_tf32(rb[i].y);                   \
            t.z = to_tf32(rb[i].z); t.w = to_tf32(rb[i].w);                   \
            *(float4*)&Bs_f[(buf) * BS_SZ + b_kr[i] * BS_STRIDE + b_c] = t;   \
        }                                                                     \
    } while (0)

    // prologue
    LDG_TILE(0);
    STS_TILE(0);
    __syncthreads();

#pragma unroll 1
    for (int it = 0; it < NIT; it++) {
        const int buf = it & 1;
        if (it + 1 < NIT) LDG_TILE((it + 1) * BK);

        const float* Asr = As_f + buf * AS_SZ;
        const float* Bsr = Bs_f + buf * BS_SZ;

#pragma unroll
        for (int ks = 0; ks < 4; ks++) {
            const int kb = ks * 8;
            float a[2][4];
#pragma unroll
            for (int mt = 0; mt < 2; mt++) {
                const int r = warp_m * 32 + mt * 16 + gid;
                a[mt][0] = Asr[r * AS_STRIDE + kb + tig];
                a[mt][1] = Asr[(r + 8) * AS_STRIDE + kb + tig];
                a[mt][2] = Asr[r * AS_STRIDE + kb + tig + 4];
                a[mt][3] = Asr[(r + 8) * AS_STRIDE + kb + tig + 4];
            }
            float b[8][2];
#pragma unroll
            for (int nt = 0; nt < 8; nt++) {
                const int cn = warp_n * 64 + nt * 8 + gid;
                b[nt][0] = Bsr[(kb + tig) * BS_STRIDE + cn];
                b[nt][1] = Bsr[(kb + tig + 4) * BS_STRIDE + cn];
            }
#pragma unroll
            for (int mt = 0; mt < 2; mt++)
#pragma unroll
                for (int nt = 0; nt < 8; nt++)
                    mma_tf32(acc[mt][nt], a[mt], b[nt][0], b[nt][1]);
        }

        // STS after compute: the single end-of-iter barrier covers both
        // hazards (prev-iter readers of buf^1 finished before this barrier's
        // predecessor; next-iter readers of buf^1 start after this barrier).
        if (it + 1 < NIT) {
            STS_TILE(buf ^ 1);
            __syncthreads();
        }
    }

    // ---- epilogue: fragment-direct stores + bias ----
#pragma unroll
    for (int nt = 0; nt < 8; nt++) {
        const int cn = n0 + warp_n * 64 + nt * 8 + 2 * tig;
        const float2 bb = *(const float2*)&bias[cn];
#pragma unroll
        for (int mt = 0; mt < 2; mt++) {
            const int r = m0 + warp_m * 32 + mt * 16 + gid;
            float2 v0 = make_float2(acc[mt][nt][0] + bb.x, acc[mt][nt][1] + bb.y);
            float2 v1 = make_float2(acc[mt][nt][2] + bb.x, acc[mt][nt][3] + bb.y);
            if (QKV) {
                v0.x = to_tf32(v0.x); v0.y = to_tf32(v0.y);
                v1.x = to_tf32(v1.x); v1.y = to_tf32(v1.y);
            }
            *(float2*)&C[(size_t)r * D_MODEL + cn] = v0;
            *(float2*)&C[(size_t)(r + 8) * D_MODEL + cn] = v1;
        }
    }
#undef LDG_TILE
#undef STS_TILE
}

// ===========================================================================
// Tensor-core flash attention (tf32 mma.sync). Same as the passing R8
// version except __launch_bounds__(256, 2) to get 2 CTAs/SM.
// ===========================================================================
#define K_STRIDE 68
#define V_STRIDE 72
#define PS_STRIDE 76
#define KBUF     (64 * K_STRIDE)
#define VBUF     (64 * V_STRIDE)

__global__ void __launch_bounds__(256, 2)
attention_kernel(const float* __restrict__ Q, const float* __restrict__ K,
                 const float* __restrict__ V, float* __restrict__ O) {
    extern __shared__ float smem[];
    float* Ks = smem;                    // [2][64][K_STRIDE]
    float* Vs = Ks + 2 * KBUF;           // [2][64][V_STRIDE]
    float* Ps = Vs + 2 * VBUF;           // [128][PS_STRIDE]  (also Q staging)

    const int tid = threadIdx.x;
    const int lane = tid & 31;
    const int wid = tid >> 5;
    const int gid = lane >> 2;
    const int tig = lane & 3;
    const int b = blockIdx.y / NH;
    const int h = blockIdx.y % NH;
    const size_t base = (size_t)b * SEQ * D_MODEL + (size_t)h * DHEAD;
    const int q0 = blockIdx.x * 128;

    const uint32_t smem_b = smem_u32(smem);
    const uint32_t ks_b = smem_b;
    const uint32_t vs_b = smem_b + 2 * KBUF * 4;
    const uint32_t ps_b = smem_b + (2 * KBUF + 2 * VBUF) * 4;

#pragma unroll
    for (int i = 0; i < 8; i++) {
        const int id = tid + i * 256;
        const int r = id >> 4, c4 = (id & 15) * 4;
        CP_ASYNC16(ps_b + (r * PS_STRIDE + c4) * 4,
                   Q + base + (size_t)(q0 + r) * D_MODEL + c4);
    }
    CP_COMMIT();

#define LOAD_KV(kt, buf)                                                      \
    do {                                                                      \
        _Pragma("unroll")                                                     \
        for (int i = 0; i < 4; i++) {                                         \
            const int id = tid + i * 256;                                     \
            const int r = id >> 4, c4 = (id & 15) * 4;                        \
            const size_t go = base + (size_t)((kt) * 64 + r) * D_MODEL + c4;  \
            CP_ASYNC16(ks_b + ((buf) * KBUF + r * K_STRIDE + c4) * 4, K + go); \
            CP_ASYNC16(vs_b + ((buf) * VBUF + r * V_STRIDE + c4) * 4, V + go); \
        }                                                                     \
        CP_COMMIT();                                                          \
    } while (0)

    LOAD_KV(0, 0);
    LOAD_KV(1, 1);

    CP_WAIT(2);
    __syncthreads();

    float qf[8][4];
    {
        const int r0 = (wid * 16 + gid) * PS_STRIDE;
        const int r1 = (wid * 16 + gid + 8) * PS_STRIDE;
#pragma unroll
        for (int kc = 0; kc < 8; kc++) {
            const int c = kc * 8 + tig;
            qf[kc][0] = to_tf32(0.125f * Ps[r0 + c]);
            qf[kc][1] = to_tf32(0.125f * Ps[r1 + c]);
            qf[kc][2] = to_tf32(0.125f * Ps[r0 + c + 4]);
            qf[kc][3] = to_tf32(0.125f * Ps[r1 + c + 4]);
        }
    }
    __syncthreads();

    float o_acc[8][4];
#pragma unroll
    for (int nt = 0; nt < 8; nt++)
#pragma unroll
        for (int i = 0; i < 4; i++) o_acc[nt][i] = 0.0f;
    float m0r = -1e30f, m1r = -1e30f, l0r = 0.0f, l1r = 0.0f;

    float* Pw = Ps + wid * 16 * PS_STRIDE;

#pragma unroll 1
    for (int kt = 0; kt < 16; kt++) {
        if (kt < 15) { CP_WAIT(1); } else { CP_WAIT(0); }
        __syncthreads();
        const float* KsC = Ks + (kt & 1) * KBUF;
        const float* VsC = Vs + (kt & 1) * VBUF;

        float s[8][4];
#pragma unroll
        for (int nt = 0; nt < 8; nt++)
#pragma unroll
            for (int i = 0; i < 4; i++) s[nt][i] = 0.0f;

#pragma unroll
        for (int kc = 0; kc < 8; kc++) {
            float bk0[8], bk1[8];
#pragma unroll
            for (int nt = 0; nt < 8; nt++) {
                const int jr = (nt * 8 + gid) * K_STRIDE + kc * 8 + tig;
                bk0[nt] = KsC[jr];
                bk1[nt] = KsC[jr + 4];
            }
#pragma unroll
            for (int nt = 0; nt < 8; nt++)
                mma_tf32(s[nt], qf[kc], bk0[nt], bk1[nt]);
        }

        float mx0 = s[0][0], mx1 = s[0][2];
#pragma unroll
        for (int nt = 0; nt < 8; nt++) {
            mx0 = fmaxf(mx0, fmaxf(s[nt][0], s[nt][1]));
            mx1 = fmaxf(mx1, fmaxf(s[nt][2], s[nt][3]));
        }
        mx0 = fmaxf(mx0, __shfl_xor_sync(0xffffffffu, mx0, 1));
        mx0 = fmaxf(mx0, __shfl_xor_sync(0xffffffffu, mx0, 2));
        mx1 = fmaxf(mx1, __shfl_xor_sync(0xffffffffu, mx1, 1));
        mx1 = fmaxf(mx1, __shfl_xor_sync(0xffffffffu, mx1, 2));

        const float nm0 = fmaxf(m0r, mx0);
        const float nm1 = fmaxf(m1r, mx1);
        const float fac0 = __expf(m0r - nm0);
        const float fac1 = __expf(m1r - nm1);
        m0r = nm0; m1r = nm1;

        float sum0 = 0.0f, sum1 = 0.0f;
#pragma unroll
        for (int nt = 0; nt < 8; nt++) {
            s[nt][0] = __expf(s[nt][0] - nm0);
            s[nt][1] = __expf(s[nt][1] - nm0);
            s[nt][2] = __expf(s[nt][2] - nm1);
            s[nt][3] = __expf(s[nt][3] - nm1);
            sum0 += s[nt][0] + s[nt][1];
            sum1 += s[nt][2] + s[nt][3];
        }
        sum0 += __shfl_xor_sync(0xffffffffu, sum0, 1);
        sum0 += __shfl_xor_sync(0xffffffffu, sum0, 2);
        sum1 += __shfl_xor_sync(0xffffffffu, sum1, 1);
        sum1 += __shfl_xor_sync(0xffffffffu, sum1, 2);
        l0r = l0r * fac0 + sum0;
        l1r = l1r * fac1 + sum1;

#pragma unroll
        for (int nt = 0; nt < 8; nt++) {
            o_acc[nt][0] *= fac0; o_acc[nt][1] *= fac0;
            o_acc[nt][2] *= fac1; o_acc[nt][3] *= fac1;
        }

#pragma unroll
        for (int nt = 0; nt < 8; nt++) {
            const int c = nt * 8 + 2 * tig;
            *(float2*)&Pw[gid * PS_STRIDE + c] =
                make_float2(to_tf32(s[nt][0]), to_tf32(s[nt][1]));
            *(float2*)&Pw[(gid + 8) * PS_STRIDE + c] =
                make_float2(to_tf32(s[nt][2]), to_tf32(s[nt][3]));
        }
        __syncwarp();

#pragma unroll
        for (int kc = 0; kc < 8; kc++) {
            float pa[4];
            const int c = kc * 8 + tig;
            pa[0] = Pw[gid * PS_STRIDE + c];
            pa[1] = Pw[(gid + 8) * PS_STRIDE + c];
            pa[2] = Pw[gid * PS_STRIDE + c + 4];
            pa[3] = Pw[(gid + 8) * PS_STRIDE + c + 4];
            float bv0[8], bv1[8];
            const int vr0 = (kc * 8 + tig) * V_STRIDE;
            const int vr1 = (kc * 8 + tig + 4) * V_STRIDE;
#pragma unroll
            for (int nt = 0; nt < 8; nt++) {
                bv0[nt] = VsC[vr0 + nt * 8 + gid];
                bv1[nt] = VsC[vr1 + nt * 8 + gid];
            }
#pragma unroll
            for (int nt = 0; nt < 8; nt++)
                mma_tf32(o_acc[nt], pa, bv0[nt], bv1[nt]);
        }

        __syncthreads();
        if (kt + 2 < 16) LOAD_KV(kt + 2, kt & 1);
    }

    const float inv0 = 1.0f / l0r;
    const float inv1 = 1.0f / l1r;
    const int r0 = q0 + wid * 16 + gid;
#pragma unroll
    for (int nt = 0; nt < 8; nt++) {
        const int c = nt * 8 + 2 * tig;
        *(float2*)&O[base + (size_t)r0 * D_MODEL + c] =
            make_float2(o_acc[nt][0] * inv0, o_acc[nt][1] * inv0);
        *(float2*)&O[base + (size_t)(r0 + 8) * D_MODEL + c] =
            make_float2(o_acc[nt][2] * inv1, o_acc[nt][3] * inv1);
    }
#undef LOAD_KV
}

// ---------------------------------------------------------------------------
extern "C" void kernel_launch(void* const* d_in, const int* in_sizes, int n_in,
                              void* d_out, int out_size) {
    (void)in_sizes; (void)n_in; (void)out_size;
    const float* x  = (const float*)d_in[0];
    const float* Wq = (const float*)d_in[1];
    const float* bq = (const float*)d_in[2];
    const float* Wk = (const float*)d_in[3];
    const float* bk = (const float*)d_in[4];
    const float* Wv = (const float*)d_in[5];
    const float* bv = (const float*)d_in[6];
    const float* Wo = (const float*)d_in[7];
    const float* bo = (const float*)d_in[8];
    float* out = (float*)d_out;

    float *q, *k, *v, *attn;
    cudaGetSymbolAddress((void**)&q, g_q);
    cudaGetSymbolAddress((void**)&k, g_k);
    cudaGetSymbolAddress((void**)&v, g_v);
    cudaGetSymbolAddress((void**)&attn, g_attn);

    const int smem_gemm = 2 * (AS_SZ + BS_SZ) * (int)sizeof(float); // 71680
    cudaFuncSetAttribute(mma_gemm_kernel<0>,
                         cudaFuncAttributeMaxDynamicSharedMemorySize, smem_gemm);
    cudaFuncSetAttribute(mma_gemm_kernel<1>,
                         cudaFuncAttributeMaxDynamicSharedMemorySize, smem_gemm);
    const int smem_attn =
        (2 * KBUF + 2 * VBUF + 128 * PS_STRIDE) * (int)sizeof(float); // 110592
    cudaFuncSetAttribute(attention_kernel,
                         cudaFuncAttributeMaxDynamicSharedMemorySize, smem_attn);

    // Fused QKV projection: one launch, blockIdx.z selects Q/K/V
    dim3 qkv_grid(D_MODEL / 128, TOK / 128, 3);   // (6, 64, 3) = 1152 CTAs
    mma_gemm_kernel<1><<<qkv_grid, 256, smem_gemm>>>(
        x, Wq, bq, q, Wk, bk, k, Wv, bv, v);

    // Tensor-core flash attention (2 CTAs/SM)
    dim3 attn_grid(SEQ / 128, BATCH * NH);        // (8, 96)
    attention_kernel<<<attn_grid, 256, smem_attn>>>(q, k, v, attn);

    // Output projection (full fp32 output)
    dim3 gemm_grid(D_MODEL / 128, TOK / 128);     // (6, 64)
    mma_gemm_kernel<0><<<gemm_grid, 256, smem_gemm>>>(
        attn, Wo, bo, out, nullptr, nullptr, nullptr, nullptr, nullptr, nullptr);
}

// round 12
// speedup vs baseline: 1.7790x; 1.0568x over previous
#include <cuda_runtime.h>
#include <math.h>
#include <cstdint>

#define D_MODEL 768
#define NH      12
#define DHEAD   64
#define BATCH   8
#define SEQ     1024
#define TOK     (BATCH * SEQ)   // 8192

// Scratch (device globals — no runtime allocation allowed)
__device__ float g_q[TOK * D_MODEL];
__device__ float g_k[TOK * D_MODEL];
__device__ float g_v[TOK * D_MODEL];
__device__ float g_attn[TOK * D_MODEL];
__device__ float g_xr[TOK * D_MODEL];        // x rounded to tf32
__device__ float g_wqr[D_MODEL * D_MODEL];   // weights rounded to tf32
__device__ float g_wkr[D_MODEL * D_MODEL];
__device__ float g_wvr[D_MODEL * D_MODEL];
__device__ float g_wor[D_MODEL * D_MODEL];

__device__ __forceinline__ float to_tf32(float x) {
    float r;
    asm("cvt.rna.tf32.f32 %0, %1;" : "=f"(r) : "f"(x));
    return r;
}

__device__ __forceinline__ uint32_t smem_u32(const void* p) {
    uint32_t a;
    asm("{ .reg .u64 t; cvta.to.shared.u64 t, %1; cvt.u32.u64 %0, t; }"
        : "=r"(a) : "l"(p));
    return a;
}

// c += a @ b  (m16n8k8 tf32, fp32 accum)
__device__ __forceinline__ void mma_tf32(float* c, const float* a, float b0, float b1) {
    asm volatile(
        "mma.sync.aligned.m16n8k8.row.col.f32.tf32.tf32.f32 "
        "{%0,%1,%2,%3}, {%4,%5,%6,%7}, {%8,%9}, {%0,%1,%2,%3};"
        : "+f"(c[0]), "+f"(c[1]), "+f"(c[2]), "+f"(c[3])
        : "r"(__float_as_uint(a[0])), "r"(__float_as_uint(a[1])),
          "r"(__float_as_uint(a[2])), "r"(__float_as_uint(a[3])),
          "r"(__float_as_uint(b0)), "r"(__float_as_uint(b1)));
}

#define CP_ASYNC16(saddr, gptr) \
    asm volatile("cp.async.cg.shared.global [%0], [%1], 16;" \
                 :: "r"(saddr), "l"(gptr) : "memory")
#define CP_COMMIT() asm volatile("cp.async.commit_group;" ::: "memory")
#define CP_WAIT(n)  asm volatile("cp.async.wait_group %0;" :: "n"(n) : "memory")

// ===========================================================================
// Elementwise tf32 pre-rounding (float4)
// ===========================================================================
__global__ void __launch_bounds__(256)
round_tf32_kernel(const float* __restrict__ src, float* __restrict__ dst, int n4) {
    int i = blockIdx.x * blockDim.x + threadIdx.x;
    if (i < n4) {
        float4 v = ((const float4*)src)[i];
        v.x = to_tf32(v.x); v.y = to_tf32(v.y);
        v.z = to_tf32(v.z); v.w = to_tf32(v.w);
        ((float4*)dst)[i] = v;
    }
}

// ===========================================================================
// tf32 tensor-core GEMM + bias, v2.
// CTA tile 128x128, 128 threads = 4 warps (2x2), warp tile 64x64.
// 3-stage cp.async pipeline, ONE barrier per iteration.
// Inputs MUST be pre-rounded to tf32 (cp.async copies raw bytes).
// QKV=1: fused Q/K/V (blockIdx.z selects), B per-head [H, D, DH], out tf32.
// QKV=0: single GEMM, B row-major [K,N], full fp32 out (Wo).
// ===========================================================================
#define BK  32
#define NIT (D_MODEL / BK)   // 24
#define AS_STRIDE 36         // 144 B row pitch (16B multiple), frag conflict-free
#define BS_STRIDE 136        // 544 B row pitch (16B multiple), frag conflict-free
#define AS_SZ (128 * AS_STRIDE)   // 4608 floats
#define BS_SZ (BK * BS_STRIDE)    // 4352 floats
#define GSTG 3

template <int QKV>
__global__ void __launch_bounds__(128, 2)
mma_gemm_kernel(const float* __restrict__ A,
                const float* __restrict__ B0, const float* __restrict__ bias0,
                float* __restrict__ C0,
                const float* __restrict__ B1, const float* __restrict__ bias1,
                float* __restrict__ C1,
                const float* __restrict__ B2, const float* __restrict__ bias2,
                float* __restrict__ C2) {
    extern __shared__ float gsm[];
    float* As_f = gsm;                    // [GSTG][128][AS_STRIDE]
    float* Bs_f = gsm + GSTG * AS_SZ;     // [GSTG][BK][BS_STRIDE]

    const float* B    = B0;
    const float* bias = bias0;
    float*       C    = C0;
    if (QKV) {
        if (blockIdx.z == 1) { B = B1; bias = bias1; C = C1; }
        else if (blockIdx.z == 2) { B = B2; bias = bias2; C = C2; }
    }

    const int tid = threadIdx.x;
    const int lane = tid & 31;
    const int wid = tid >> 5;
    const int gid = lane >> 2;
    const int tig = lane & 3;
    const int warp_m = wid & 1;    // 64-row band
    const int warp_n = wid >> 1;   // 64-col band
    const int m0 = blockIdx.y * 128;
    const int n0 = blockIdx.x * 128;

    const uint32_t as_b = smem_u32(As_f);
    const uint32_t bs_b = smem_u32(Bs_f);

    // Loader mapping: A tile 128x32 = 1024 float4, 8/thread (row=id>>3).
    //                 B tile 32x128 = 1024 float4, 8/thread (krow=id>>5).
    const int a_col = (tid & 7) * 4;
    const int b_c   = (tid & 31) * 4;
    const float* aptr[8];
    const float* bptr[8];
    uint32_t a_dst[8], b_dst[8];
#pragma unroll
    for (int i = 0; i < 8; i++) {
        const int ar = (tid + i * 128) >> 3;         // 0..127
        const int bkr = (tid + i * 128) >> 5;        // 0..31
        aptr[i] = A + (size_t)(m0 + ar) * D_MODEL + a_col;
        a_dst[i] = as_b + (ar * AS_STRIDE + a_col) * 4;
        b_dst[i] = bs_b + (bkr * BS_STRIDE + b_c) * 4;
        if (QKV == 0) {
            bptr[i] = B + (size_t)bkr * D_MODEL + n0 + b_c;
        } else {
            const int c = n0 + b_c;
            bptr[i] = B + ((size_t)(c >> 6) * D_MODEL + bkr) * DHEAD + (c & 63);
        }
    }
    // per-k0 advance: A +BK floats; B: QKV? +BK*DHEAD : +BK*D_MODEL
    const int b_adv = (QKV == 0) ? BK * D_MODEL : BK * DHEAD;

#define LOAD_STAGE(koff_a, koff_b, st)                                        \
    do {                                                                      \
        _Pragma("unroll")                                                     \
        for (int i = 0; i < 8; i++)                                           \
            CP_ASYNC16(a_dst[i] + (st) * (AS_SZ * 4), aptr[i] + (koff_a));    \
        _Pragma("unroll")                                                     \
        for (int i = 0; i < 8; i++)                                           \
            CP_ASYNC16(b_dst[i] + (st) * (BS_SZ * 4), bptr[i] + (koff_b));    \
        CP_COMMIT();                                                          \
    } while (0)

    float acc[4][8][4];
#pragma unroll
    for (int mt = 0; mt < 4; mt++)
#pragma unroll
        for (int nt = 0; nt < 8; nt++)
#pragma unroll
            for (int i = 0; i < 4; i++) acc[mt][nt][i] = 0.0f;

    LOAD_STAGE(0, 0, 0);
    LOAD_STAGE(BK, b_adv, 1);

    int st = 0;   // it % 3
#pragma unroll 1
    for (int it = 0; it < NIT; it++) {
        CP_WAIT(1);
        __syncthreads();

        // issue stage it+2 into buffer (it+2)%3 — its previous readers (iter
        // it-1) finished before the barrier above.
        const int st2 = (st + 2 >= GSTG) ? st + 2 - GSTG : st + 2;
        if (it + 2 < NIT) {
            LOAD_STAGE((it + 2) * BK, (it + 2) * b_adv, st2);
        } else {
            CP_COMMIT();     // empty group: keeps WAIT(1) meaning "stage it done"
        }

        const float* Asr = As_f + st * AS_SZ;
        const float* Bsr = Bs_f + st * BS_SZ;

#pragma unroll
        for (int ks = 0; ks < 4; ks++) {
            const int kb = ks * 8;
            float a[4][4];
#pragma unroll
            for (int mt = 0; mt < 4; mt++) {
                const int r = warp_m * 64 + mt * 16 + gid;
                a[mt][0] = Asr[r * AS_STRIDE + kb + tig];
                a[mt][1] = Asr[(r + 8) * AS_STRIDE + kb + tig];
                a[mt][2] = Asr[r * AS_STRIDE + kb + tig + 4];
                a[mt][3] = Asr[(r + 8) * AS_STRIDE + kb + tig + 4];
            }
            float b[8][2];
#pragma unroll
            for (int nt = 0; nt < 8; nt++) {
                const int cn = warp_n * 64 + nt * 8 + gid;
                b[nt][0] = Bsr[(kb + tig) * BS_STRIDE + cn];
                b[nt][1] = Bsr[(kb + tig + 4) * BS_STRIDE + cn];
            }
#pragma unroll
            for (int mt = 0; mt < 4; mt++)
#pragma unroll
                for (int nt = 0; nt < 8; nt++)
                    mma_tf32(acc[mt][nt], a[mt], b[nt][0], b[nt][1]);
        }

        st = (st + 1 >= GSTG) ? 0 : st + 1;
    }

    // ---- epilogue: fragment-direct stores + bias ----
#pragma unroll
    for (int nt = 0; nt < 8; nt++) {
        const int cn = n0 + warp_n * 64 + nt * 8 + 2 * tig;
        const float2 bb = *(const float2*)&bias[cn];
#pragma unroll
        for (int mt = 0; mt < 4; mt++) {
            const int r = m0 + warp_m * 64 + mt * 16 + gid;
            float2 v0 = make_float2(acc[mt][nt][0] + bb.x, acc[mt][nt][1] + bb.y);
            float2 v1 = make_float2(acc[mt][nt][2] + bb.x, acc[mt][nt][3] + bb.y);
            if (QKV) {
                v0.x = to_tf32(v0.x); v0.y = to_tf32(v0.y);
                v1.x = to_tf32(v1.x); v1.y = to_tf32(v1.y);
            }
            *(float2*)&C[(size_t)r * D_MODEL + cn] = v0;
            *(float2*)&C[(size_t)(r + 8) * D_MODEL + cn] = v1;
        }
    }
#undef LOAD_STAGE
}

// ===========================================================================
// Tensor-core flash attention (tf32 mma.sync). Same as passing R10 version,
// plus tf32 rounding of the output (Wo GEMM reads it via cp.async now).
// ===========================================================================
#define K_STRIDE 68
#define V_STRIDE 72
#define PS_STRIDE 76
#define KBUF     (64 * K_STRIDE)
#define VBUF     (64 * V_STRIDE)

__global__ void __launch_bounds__(256, 2)
attention_kernel(const float* __restrict__ Q, const float* __restrict__ K,
                 const float* __restrict__ V, float* __restrict__ O) {
    extern __shared__ float smem[];
    float* Ks = smem;                    // [2][64][K_STRIDE]
    float* Vs = Ks + 2 * KBUF;           // [2][64][V_STRIDE]
    float* Ps = Vs + 2 * VBUF;           // [128][PS_STRIDE]  (also Q staging)

    const int tid = threadIdx.x;
    const int lane = tid & 31;
    const int wid = tid >> 5;
    const int gid = lane >> 2;
    const int tig = lane & 3;
    const int b = blockIdx.y / NH;
    const int h = blockIdx.y % NH;
    const size_t base = (size_t)b * SEQ * D_MODEL + (size_t)h * DHEAD;
    const int q0 = blockIdx.x * 128;

    const uint32_t smem_b = smem_u32(smem);
    const uint32_t ks_b = smem_b;
    const uint32_t vs_b = smem_b + 2 * KBUF * 4;
    const uint32_t ps_b = smem_b + (2 * KBUF + 2 * VBUF) * 4;

#pragma unroll
    for (int i = 0; i < 8; i++) {
        const int id = tid + i * 256;
        const int r = id >> 4, c4 = (id & 15) * 4;
        CP_ASYNC16(ps_b + (r * PS_STRIDE + c4) * 4,
                   Q + base + (size_t)(q0 + r) * D_MODEL + c4);
    }
    CP_COMMIT();

#define LOAD_KV(kt, buf)                                                      \
    do {                                                                      \
        _Pragma("unroll")                                                     \
        for (int i = 0; i < 4; i++) {                                         \
            const int id = tid + i * 256;                                     \
            const int r = id >> 4, c4 = (id & 15) * 4;                        \
            const size_t go = base + (size_t)((kt) * 64 + r) * D_MODEL + c4;  \
            CP_ASYNC16(ks_b + ((buf) * KBUF + r * K_STRIDE + c4) * 4, K + go); \
            CP_ASYNC16(vs_b + ((buf) * VBUF + r * V_STRIDE + c4) * 4, V + go); \
        }                                                                     \
        CP_COMMIT();                                                          \
    } while (0)

    LOAD_KV(0, 0);
    LOAD_KV(1, 1);

    CP_WAIT(2);
    __syncthreads();

    float qf[8][4];
    {
        const int r0 = (wid * 16 + gid) * PS_STRIDE;
        const int r1 = (wid * 16 + gid + 8) * PS_STRIDE;
#pragma unroll
        for (int kc = 0; kc < 8; kc++) {
            const int c = kc * 8 + tig;
            qf[kc][0] = to_tf32(0.125f * Ps[r0 + c]);
            qf[kc][1] = to_tf32(0.125f * Ps[r1 + c]);
            qf[kc][2] = to_tf32(0.125f * Ps[r0 + c + 4]);
            qf[kc][3] = to_tf32(0.125f * Ps[r1 + c + 4]);
        }
    }
    __syncthreads();

    float o_acc[8][4];
#pragma unroll
    for (int nt = 0; nt < 8; nt++)
#pragma unroll
        for (int i = 0; i < 4; i++) o_acc[nt][i] = 0.0f;
    float m0r = -1e30f, m1r = -1e30f, l0r = 0.0f, l1r = 0.0f;

    float* Pw = Ps + wid * 16 * PS_STRIDE;

#pragma unroll 1
    for (int kt = 0; kt < 16; kt++) {
        if (kt < 15) { CP_WAIT(1); } else { CP_WAIT(0); }
        __syncthreads();
        const float* KsC = Ks + (kt & 1) * KBUF;
        const float* VsC = Vs + (kt & 1) * VBUF;

        float s[8][4];
#pragma unroll
        for (int nt = 0; nt < 8; nt++)
#pragma unroll
            for (int i = 0; i < 4; i++) s[nt][i] = 0.0f;

#pragma unroll
        for (int kc = 0; kc < 8; kc++) {
            float bk0[8], bk1[8];
#pragma unroll
            for (int nt = 0; nt < 8; nt++) {
                const int jr = (nt * 8 + gid) * K_STRIDE + kc * 8 + tig;
                bk0[nt] = KsC[jr];
                bk1[nt] = KsC[jr + 4];
            }
#pragma unroll
            for (int nt = 0; nt < 8; nt++)
                mma_tf32(s[nt], qf[kc], bk0[nt], bk1[nt]);
        }

        float mx0 = s[0][0], mx1 = s[0][2];
#pragma unroll
        for (int nt = 0; nt < 8; nt++) {
            mx0 = fmaxf(mx0, fmaxf(s[nt][0], s[nt][1]));
            mx1 = fmaxf(mx1, fmaxf(s[nt][2], s[nt][3]));
        }
        mx0 = fmaxf(mx0, __shfl_xor_sync(0xffffffffu, mx0, 1));
        mx0 = fmaxf(mx0, __shfl_xor_sync(0xffffffffu, mx0, 2));
        mx1 = fmaxf(mx1, __shfl_xor_sync(0xffffffffu, mx1, 1));
        mx1 = fmaxf(mx1, __shfl_xor_sync(0xffffffffu, mx1, 2));

        const float nm0 = fmaxf(m0r, mx0);
        const float nm1 = fmaxf(m1r, mx1);
        const float fac0 = __expf(m0r - nm0);
        const float fac1 = __expf(m1r - nm1);
        m0r = nm0; m1r = nm1;

        float sum0 = 0.0f, sum1 = 0.0f;
#pragma unroll
        for (int nt = 0; nt < 8; nt++) {
            s[nt][0] = __expf(s[nt][0] - nm0);
            s[nt][1] = __expf(s[nt][1] - nm0);
            s[nt][2] = __expf(s[nt][2] - nm1);
            s[nt][3] = __expf(s[nt][3] - nm1);
            sum0 += s[nt][0] + s[nt][1];
            sum1 += s[nt][2] + s[nt][3];
        }
        sum0 += __shfl_xor_sync(0xffffffffu, sum0, 1);
        sum0 += __shfl_xor_sync(0xffffffffu, sum0, 2);
        sum1 += __shfl_xor_sync(0xffffffffu, sum1, 1);
        sum1 += __shfl_xor_sync(0xffffffffu, sum1, 2);
        l0r = l0r * fac0 + sum0;
        l1r = l1r * fac1 + sum1;

#pragma unroll
        for (int nt = 0; nt < 8; nt++) {
            o_acc[nt][0] *= fac0; o_acc[nt][1] *= fac0;
            o_acc[nt][2] *= fac1; o_acc[nt][3] *= fac1;
        }

#pragma unroll
        for (int nt = 0; nt < 8; nt++) {
            const int c = nt * 8 + 2 * tig;
            *(float2*)&Pw[gid * PS_STRIDE + c] =
                make_float2(to_tf32(s[nt][0]), to_tf32(s[nt][1]));
            *(float2*)&Pw[(gid + 8) * PS_STRIDE + c] =
                make_float2(to_tf32(s[nt][2]), to_tf32(s[nt][3]));
        }
        __syncwarp();

#pragma unroll
        for (int kc = 0; kc < 8; kc++) {
            float pa[4];
            const int c = kc * 8 + tig;
            pa[0] = Pw[gid * PS_STRIDE + c];
            pa[1] = Pw[(gid + 8) * PS_STRIDE + c];
            pa[2] = Pw[gid * PS_STRIDE + c + 4];
            pa[3] = Pw[(gid + 8) * PS_STRIDE + c + 4];
            float bv0[8], bv1[8];
            const int vr0 = (kc * 8 + tig) * V_STRIDE;
            const int vr1 = (kc * 8 + tig + 4) * V_STRIDE;
#pragma unroll
            for (int nt = 0; nt < 8; nt++) {
                bv0[nt] = VsC[vr0 + nt * 8 + gid];
                bv1[nt] = VsC[vr1 + nt * 8 + gid];
            }
#pragma unroll
            for (int nt = 0; nt < 8; nt++)
                mma_tf32(o_acc[nt], pa, bv0[nt], bv1[nt]);
        }

        __syncthreads();
        if (kt + 2 < 16) LOAD_KV(kt + 2, kt & 1);
    }

    const float inv0 = 1.0f / l0r;
    const float inv1 = 1.0f / l1r;
    const int r0 = q0 + wid * 16 + gid;
#pragma unroll
    for (int nt = 0; nt < 8; nt++) {
        const int c = nt * 8 + 2 * tig;
        *(float2*)&O[base + (size_t)r0 * D_MODEL + c] =
            make_float2(to_tf32(o_acc[nt][0] * inv0), to_tf32(o_acc[nt][1] * inv0));
        *(float2*)&O[base + (size_t)(r0 + 8) * D_MODEL + c] =
            make_float2(to_tf32(o_acc[nt][2] * inv1), to_tf32(o_acc[nt][3] * inv1));
    }
#undef LOAD_KV
}

// ---------------------------------------------------------------------------
extern "C" void kernel_launch(void* const* d_in, const int* in_sizes, int n_in,
                              void* d_out, int out_size) {
    (void)in_sizes; (void)n_in; (void)out_size;
    const float* x  = (const float*)d_in[0];
    const float* Wq = (const float*)d_in[1];
    const float* bq = (const float*)d_in[2];
    const float* Wk = (const float*)d_in[3];
    const float* bk = (const float*)d_in[4];
    const float* Wv = (const float*)d_in[5];
    const float* bv = (const float*)d_in[6];
    const float* Wo = (const float*)d_in[7];
    const float* bo = (const float*)d_in[8];
    float* out = (float*)d_out;

    float *q, *k, *v, *attn, *xr, *wqr, *wkr, *wvr, *wor;
    cudaGetSymbolAddress((void**)&q, g_q);
    cudaGetSymbolAddress((void**)&k, g_k);
    cudaGetSymbolAddress((void**)&v, g_v);
    cudaGetSymbolAddress((void**)&attn, g_attn);
    cudaGetSymbolAddress((void**)&xr, g_xr);
    cudaGetSymbolAddress((void**)&wqr, g_wqr);
    cudaGetSymbolAddress((void**)&wkr, g_wkr);
    cudaGetSymbolAddress((void**)&wvr, g_wvr);
    cudaGetSymbolAddress((void**)&wor, g_wor);

    const int smem_gemm = GSTG * (AS_SZ + BS_SZ) * (int)sizeof(float); // 107520
    cudaFuncSetAttribute(mma_gemm_kernel<0>,
                         cudaFuncAttributeMaxDynamicSharedMemorySize, smem_gemm);
    cudaFuncSetAttribute(mma_gemm_kernel<1>,
                         cudaFuncAttributeMaxDynamicSharedMemorySize, smem_gemm);
    const int smem_attn =
        (2 * KBUF + 2 * VBUF + 128 * PS_STRIDE) * (int)sizeof(float); // 110592
    cudaFuncSetAttribute(attention_kernel,
                         cudaFuncAttributeMaxDynamicSharedMemorySize, smem_attn);

    // Pre-round x + weights to tf32 (cp.async copies raw bytes; HW truncation
    // of pre-rounded values is exact).
    const int xn4 = TOK * D_MODEL / 4;
    const int wn4 = D_MODEL * D_MODEL / 4;
    round_tf32_kernel<<<(xn4 + 255) / 256, 256>>>(x, xr, xn4);
    round_tf32_kernel<<<(wn4 + 255) / 256, 256>>>(Wq, wqr, wn4);
    round_tf32_kernel<<<(wn4 + 255) / 256, 256>>>(Wk, wkr, wn4);
    round_tf32_kernel<<<(wn4 + 255) / 256, 256>>>(Wv, wvr, wn4);
    round_tf32_kernel<<<(wn4 + 255) / 256, 256>>>(Wo, wor, wn4);

    // Fused QKV projection: one launch, blockIdx.z selects Q/K/V
    dim3 qkv_grid(D_MODEL / 128, TOK / 128, 3);   // (6, 64, 3)
    mma_gemm_kernel<1><<<qkv_grid, 128, smem_gemm>>>(
        xr, wqr, bq, q, wkr, bk, k, wvr, bv, v);

    // Tensor-core flash attention (2 CTAs/SM)
    dim3 attn_grid(SEQ / 128, BATCH * NH);        // (8, 96)
    attention_kernel<<<attn_grid, 256, smem_attn>>>(q, k, v, attn);

    // Output projection (full fp32 output)
    dim3 gemm_grid(D_MODEL / 128, TOK / 128);     // (6, 64)
    mma_gemm_kernel<0><<<gemm_grid, 128, smem_gemm>>>(
        attn, wor, bo, out, nullptr, nullptr, nullptr, nullptr, nullptr, nullptr);
}

// round 13
// speedup vs baseline: 1.8391x; 1.0338x over previous
#include <cuda_runtime.h>
#include <math.h>
#include <cstdint>

#define D_MODEL 768
#define NH      12
#define DHEAD   64
#define BATCH   8
#define SEQ     1024
#define TOK     (BATCH * SEQ)   // 8192

// Scratch (device globals — no runtime allocation allowed)
__device__ float g_q[TOK * D_MODEL];
__device__ float g_k[TOK * D_MODEL];
__device__ float g_v[TOK * D_MODEL];
__device__ float g_attn[TOK * D_MODEL];
__device__ float g_xr[TOK * D_MODEL];        // x rounded to tf32
__device__ float g_wqr[D_MODEL * D_MODEL];   // weights rounded to tf32
__device__ float g_wkr[D_MODEL * D_MODEL];
__device__ float g_wvr[D_MODEL * D_MODEL];
__device__ float g_wor[D_MODEL * D_MODEL];

__device__ __forceinline__ float to_tf32(float x) {
    float r;
    asm("cvt.rna.tf32.f32 %0, %1;" : "=f"(r) : "f"(x));
    return r;
}

__device__ __forceinline__ uint32_t smem_u32(const void* p) {
    uint32_t a;
    asm("{ .reg .u64 t; cvta.to.shared.u64 t, %1; cvt.u32.u64 %0, t; }"
        : "=r"(a) : "l"(p));
    return a;
}

// c += a @ b  (m16n8k8 tf32, fp32 accum)
__device__ __forceinline__ void mma_tf32(float* c, const float* a, float b0, float b1) {
    asm volatile(
        "mma.sync.aligned.m16n8k8.row.col.f32.tf32.tf32.f32 "
        "{%0,%1,%2,%3}, {%4,%5,%6,%7}, {%8,%9}, {%0,%1,%2,%3};"
        : "+f"(c[0]), "+f"(c[1]), "+f"(c[2]), "+f"(c[3])
        : "r"(__float_as_uint(a[0])), "r"(__float_as_uint(a[1])),
          "r"(__float_as_uint(a[2])), "r"(__float_as_uint(a[3])),
          "r"(__float_as_uint(b0)), "r"(__float_as_uint(b1)));
}

#define LDMATRIX_X4(r0, r1, r2, r3, addr)                                     \
    asm volatile("ldmatrix.sync.aligned.m8n8.x4.shared.b16 {%0,%1,%2,%3}, [%4];" \
                 : "=r"(r0), "=r"(r1), "=r"(r2), "=r"(r3) : "r"(addr))

#define CP_ASYNC16(saddr, gptr) \
    asm volatile("cp.async.cg.shared.global [%0], [%1], 16;" \
                 :: "r"(saddr), "l"(gptr) : "memory")
#define CP_COMMIT() asm volatile("cp.async.commit_group;" ::: "memory")
#define CP_WAIT(n)  asm volatile("cp.async.wait_group %0;" :: "n"(n) : "memory")

// ===========================================================================
// Elementwise tf32 pre-rounding (float4)
// ===========================================================================
__global__ void __launch_bounds__(256)
round_tf32_kernel(const float* __restrict__ src, float* __restrict__ dst, int n4) {
    int i = blockIdx.x * blockDim.x + threadIdx.x;
    if (i < n4) {
        float4 v = ((const float4*)src)[i];
        v.x = to_tf32(v.x); v.y = to_tf32(v.y);
        v.z = to_tf32(v.z); v.w = to_tf32(v.w);
        ((float4*)dst)[i] = v;
    }
}

// ===========================================================================
// tf32 tensor-core GEMM + bias, v2 (UNCHANGED from passing R11).
// CTA tile 128x128, 128 threads = 4 warps (2x2), warp tile 64x64.
// 3-stage cp.async pipeline, ONE barrier per iteration.
// ===========================================================================
#define BK  32
#define NIT (D_MODEL / BK)   // 24
#define AS_STRIDE 36
#define BS_STRIDE 136
#define AS_SZ (128 * AS_STRIDE)
#define BS_SZ (BK * BS_STRIDE)
#define GSTG 3

template <int QKV>
__global__ void __launch_bounds__(128, 2)
mma_gemm_kernel(const float* __restrict__ A,
                const float* __restrict__ B0, const float* __restrict__ bias0,
                float* __restrict__ C0,
                const float* __restrict__ B1, const float* __restrict__ bias1,
                float* __restrict__ C1,
                const float* __restrict__ B2, const float* __restrict__ bias2,
                float* __restrict__ C2) {
    extern __shared__ float gsm[];
    float* As_f = gsm;
    float* Bs_f = gsm + GSTG * AS_SZ;

    const float* B    = B0;
    const float* bias = bias0;
    float*       C    = C0;
    if (QKV) {
        if (blockIdx.z == 1) { B = B1; bias = bias1; C = C1; }
        else if (blockIdx.z == 2) { B = B2; bias = bias2; C = C2; }
    }

    const int tid = threadIdx.x;
    const int lane = tid & 31;
    const int wid = tid >> 5;
    const int gid = lane >> 2;
    const int tig = lane & 3;
    const int warp_m = wid & 1;
    const int warp_n = wid >> 1;
    const int m0 = blockIdx.y * 128;
    const int n0 = blockIdx.x * 128;

    const uint32_t as_b = smem_u32(As_f);
    const uint32_t bs_b = smem_u32(Bs_f);

    const int a_col = (tid & 7) * 4;
    const int b_c   = (tid & 31) * 4;
    const float* aptr[8];
    const float* bptr[8];
    uint32_t a_dst[8], b_dst[8];
#pragma unroll
    for (int i = 0; i < 8; i++) {
        const int ar = (tid + i * 128) >> 3;
        const int bkr = (tid + i * 128) >> 5;
        aptr[i] = A + (size_t)(m0 + ar) * D_MODEL + a_col;
        a_dst[i] = as_b + (ar * AS_STRIDE + a_col) * 4;
        b_dst[i] = bs_b + (bkr * BS_STRIDE + b_c) * 4;
        if (QKV == 0) {
            bptr[i] = B + (size_t)bkr * D_MODEL + n0 + b_c;
        } else {
            const int c = n0 + b_c;
            bptr[i] = B + ((size_t)(c >> 6) * D_MODEL + bkr) * DHEAD + (c & 63);
        }
    }
    const int b_adv = (QKV == 0) ? BK * D_MODEL : BK * DHEAD;

#define LOAD_STAGE(koff_a, koff_b, st)                                        \
    do {                                                                      \
        _Pragma("unroll")                                                     \
        for (int i = 0; i < 8; i++)                                           \
            CP_ASYNC16(a_dst[i] + (st) * (AS_SZ * 4), aptr[i] + (koff_a));    \
        _Pragma("unroll")                                                     \
        for (int i = 0; i < 8; i++)                                           \
            CP_ASYNC16(b_dst[i] + (st) * (BS_SZ * 4), bptr[i] + (koff_b));    \
        CP_COMMIT();                                                          \
    } while (0)

    float acc[4][8][4];
#pragma unroll
    for (int mt = 0; mt < 4; mt++)
#pragma unroll
        for (int nt = 0; nt < 8; nt++)
#pragma unroll
            for (int i = 0; i < 4; i++) acc[mt][nt][i] = 0.0f;

    LOAD_STAGE(0, 0, 0);
    LOAD_STAGE(BK, b_adv, 1);

    int st = 0;
#pragma unroll 1
    for (int it = 0; it < NIT; it++) {
        CP_WAIT(1);
        __syncthreads();

        const int st2 = (st + 2 >= GSTG) ? st + 2 - GSTG : st + 2;
        if (it + 2 < NIT) {
            LOAD_STAGE((it + 2) * BK, (it + 2) * b_adv, st2);
        } else {
            CP_COMMIT();
        }

        const float* Asr = As_f + st * AS_SZ;
        const float* Bsr = Bs_f + st * BS_SZ;

#pragma unroll
        for (int ks = 0; ks < 4; ks++) {
            const int kb = ks * 8;
            float a[4][4];
#pragma unroll
            for (int mt = 0; mt < 4; mt++) {
                const int r = warp_m * 64 + mt * 16 + gid;
                a[mt][0] = Asr[r * AS_STRIDE + kb + tig];
                a[mt][1] = Asr[(r + 8) * AS_STRIDE + kb + tig];
                a[mt][2] = Asr[r * AS_STRIDE + kb + tig + 4];
                a[mt][3] = Asr[(r + 8) * AS_STRIDE + kb + tig + 4];
            }
            float b[8][2];
#pragma unroll
            for (int nt = 0; nt < 8; nt++) {
                const int cn = warp_n * 64 + nt * 8 + gid;
                b[nt][0] = Bsr[(kb + tig) * BS_STRIDE + cn];
                b[nt][1] = Bsr[(kb + tig + 4) * BS_STRIDE + cn];
            }
#pragma unroll
            for (int mt = 0; mt < 4; mt++)
#pragma unroll
                for (int nt = 0; nt < 8; nt++)
                    mma_tf32(acc[mt][nt], a[mt], b[nt][0], b[nt][1]);
        }

        st = (st + 1 >= GSTG) ? 0 : st + 1;
    }

#pragma unroll
    for (int nt = 0; nt < 8; nt++) {
        const int cn = n0 + warp_n * 64 + nt * 8 + 2 * tig;
        const float2 bb = *(const float2*)&bias[cn];
#pragma unroll
        for (int mt = 0; mt < 4; mt++) {
            const int r = m0 + warp_m * 64 + mt * 16 + gid;
            float2 v0 = make_float2(acc[mt][nt][0] + bb.x, acc[mt][nt][1] + bb.y);
            float2 v1 = make_float2(acc[mt][nt][2] + bb.x, acc[mt][nt][3] + bb.y);
            if (QKV) {
                v0.x = to_tf32(v0.x); v0.y = to_tf32(v0.y);
                v1.x = to_tf32(v1.x); v1.y = to_tf32(v1.y);
            }
            *(float2*)&C[(size_t)r * D_MODEL + cn] = v0;
            *(float2*)&C[(size_t)(r + 8) * D_MODEL + cn] = v1;
        }
    }
#undef LOAD_STAGE
}

// ===========================================================================
// Tensor-core flash attention (tf32 mma.sync) — v3:
//  * K B-fragments via ldmatrix.x4 (f32-as-2xb16 trick; conflict-free @68)
//  * P A-fragments via ldmatrix.x4 (conflict-free @76)
//  * softmax in base-2: Q pre-scaled by 0.125*log2(e), exp2f everywhere
// ===========================================================================
#define K_STRIDE 68
#define V_STRIDE 72
#define PS_STRIDE 76
#define KBUF     (64 * K_STRIDE)
#define VBUF     (64 * V_STRIDE)
#define QSCALE   0.18033688011112042f   // 0.125 * log2(e)

__global__ void __launch_bounds__(256, 2)
attention_kernel(const float* __restrict__ Q, const float* __restrict__ K,
                 const float* __restrict__ V, float* __restrict__ O) {
    extern __shared__ float smem[];
    float* Ks = smem;                    // [2][64][K_STRIDE]
    float* Vs = Ks + 2 * KBUF;           // [2][64][V_STRIDE]
    float* Ps = Vs + 2 * VBUF;           // [128][PS_STRIDE]  (also Q staging)

    const int tid = threadIdx.x;
    const int lane = tid & 31;
    const int wid = tid >> 5;
    const int gid = lane >> 2;
    const int tig = lane & 3;
    const int b = blockIdx.y / NH;
    const int h = blockIdx.y % NH;
    const size_t base = (size_t)b * SEQ * D_MODEL + (size_t)h * DHEAD;
    const int q0 = blockIdx.x * 128;

    const uint32_t smem_b = smem_u32(smem);
    const uint32_t ks_b = smem_b;
    const uint32_t vs_b = smem_b + 2 * KBUF * 4;
    const uint32_t ps_b = smem_b + (2 * KBUF + 2 * VBUF) * 4;

    // ldmatrix per-lane offsets (in floats)
    // K: matrix m=lane>>3: j = 16p + ((lane>>4)&1)*8 + (lane&7); e += ((lane>>3)&1)*4
    const int k_lm = (((lane >> 4) & 1) * 8 + (lane & 7)) * K_STRIDE
                   + ((lane >> 3) & 1) * 4;
    // P: row = (lane&7) + ((lane>>3)&1)*8; col += ((lane>>4)&1)*4
    const int p_lm = ((lane & 7) + ((lane >> 3) & 1) * 8) * PS_STRIDE
                   + ((lane >> 4) & 1) * 4;

#pragma unroll
    for (int i = 0; i < 8; i++) {
        const int id = tid + i * 256;
        const int r = id >> 4, c4 = (id & 15) * 4;
        CP_ASYNC16(ps_b + (r * PS_STRIDE + c4) * 4,
                   Q + base + (size_t)(q0 + r) * D_MODEL + c4);
    }
    CP_COMMIT();

#define LOAD_KV(kt, buf)                                                      \
    do {                                                                      \
        _Pragma("unroll")                                                     \
        for (int i = 0; i < 4; i++) {                                         \
            const int id = tid + i * 256;                                     \
            const int r = id >> 4, c4 = (id & 15) * 4;                        \
            const size_t go = base + (size_t)((kt) * 64 + r) * D_MODEL + c4;  \
            CP_ASYNC16(ks_b + ((buf) * KBUF + r * K_STRIDE + c4) * 4, K + go); \
            CP_ASYNC16(vs_b + ((buf) * VBUF + r * V_STRIDE + c4) * 4, V + go); \
        }                                                                     \
        CP_COMMIT();                                                          \
    } while (0)

    LOAD_KV(0, 0);
    LOAD_KV(1, 1);

    CP_WAIT(2);
    __syncthreads();

    // Q fragments, scaled by 0.125*log2(e) (softmax runs in base 2)
    float qf[8][4];
    {
        const int r0 = (wid * 16 + gid) * PS_STRIDE;
        const int r1 = (wid * 16 + gid + 8) * PS_STRIDE;
#pragma unroll
        for (int kc = 0; kc < 8; kc++) {
            const int c = kc * 8 + tig;
            qf[kc][0] = to_tf32(QSCALE * Ps[r0 + c]);
            qf[kc][1] = to_tf32(QSCALE * Ps[r1 + c]);
            qf[kc][2] = to_tf32(QSCALE * Ps[r0 + c + 4]);
            qf[kc][3] = to_tf32(QSCALE * Ps[r1 + c + 4]);
        }
    }
    __syncthreads();

    float o_acc[8][4];
#pragma unroll
    for (int nt = 0; nt < 8; nt++)
#pragma unroll
        for (int i = 0; i < 4; i++) o_acc[nt][i] = 0.0f;
    float m0r = -1e30f, m1r = -1e30f, l0r = 0.0f, l1r = 0.0f;

    float* Pw = Ps + wid * 16 * PS_STRIDE;
    const uint32_t pw_u = ps_b + (wid * 16 * PS_STRIDE + p_lm) * 4;

#pragma unroll 1
    for (int kt = 0; kt < 16; kt++) {
        if (kt < 15) { CP_WAIT(1); } else { CP_WAIT(0); }
        __syncthreads();
        const uint32_t ksc_u = ks_b + ((kt & 1) * KBUF + k_lm) * 4;
        const float* VsC = Vs + (kt & 1) * VBUF;

        // ---- S = Q K^T : K B-frags via ldmatrix ----
        float s[8][4];
#pragma unroll
        for (int nt = 0; nt < 8; nt++)
#pragma unroll
            for (int i = 0; i < 4; i++) s[nt][i] = 0.0f;

#pragma unroll
        for (int kc = 0; kc < 8; kc++) {
#pragma unroll
            for (int p = 0; p < 4; p++) {
                uint32_t r0, r1, r2, r3;
                LDMATRIX_X4(r0, r1, r2, r3,
                            ksc_u + (16 * p * K_STRIDE + kc * 8) * 4);
                mma_tf32(s[2 * p], qf[kc],
                         __uint_as_float(r0), __uint_as_float(r1));
                mma_tf32(s[2 * p + 1], qf[kc],
                         __uint_as_float(r2), __uint_as_float(r3));
            }
        }

        // ---- online softmax (base 2) ----
        float mx0 = s[0][0], mx1 = s[0][2];
#pragma unroll
        for (int nt = 0; nt < 8; nt++) {
            mx0 = fmaxf(mx0, fmaxf(s[nt][0], s[nt][1]));
            mx1 = fmaxf(mx1, fmaxf(s[nt][2], s[nt][3]));
        }
        mx0 = fmaxf(mx0, __shfl_xor_sync(0xffffffffu, mx0, 1));
        mx0 = fmaxf(mx0, __shfl_xor_sync(0xffffffffu, mx0, 2));
        mx1 = fmaxf(mx1, __shfl_xor_sync(0xffffffffu, mx1, 1));
        mx1 = fmaxf(mx1, __shfl_xor_sync(0xffffffffu, mx1, 2));

        const float nm0 = fmaxf(m0r, mx0);
        const float nm1 = fmaxf(m1r, mx1);
        const float fac0 = exp2f(m0r - nm0);
        const float fac1 = exp2f(m1r - nm1);
        m0r = nm0; m1r = nm1;

        float sum0 = 0.0f, sum1 = 0.0f;
#pragma unroll
        for (int nt = 0; nt < 8; nt++) {
            s[nt][0] = exp2f(s[nt][0] - nm0);
            s[nt][1] = exp2f(s[nt][1] - nm0);
            s[nt][2] = exp2f(s[nt][2] - nm1);
            s[nt][3] = exp2f(s[nt][3] - nm1);
            sum0 += s[nt][0] + s[nt][1];
            sum1 += s[nt][2] + s[nt][3];
        }
        sum0 += __shfl_xor_sync(0xffffffffu, sum0, 1);
        sum0 += __shfl_xor_sync(0xffffffffu, sum0, 2);
        sum1 += __shfl_xor_sync(0xffffffffu, sum1, 1);
        sum1 += __shfl_xor_sync(0xffffffffu, sum1, 2);
        l0r = l0r * fac0 + sum0;
        l1r = l1r * fac1 + sum1;

#pragma unroll
        for (int nt = 0; nt < 8; nt++) {
            o_acc[nt][0] *= fac0; o_acc[nt][1] *= fac0;
            o_acc[nt][2] *= fac1; o_acc[nt][3] *= fac1;
        }

        // ---- stage P (warp-private) ----
#pragma unroll
        for (int nt = 0; nt < 8; nt++) {
            const int c = nt * 8 + 2 * tig;
            *(float2*)&Pw[gid * PS_STRIDE + c] =
                make_float2(to_tf32(s[nt][0]), to_tf32(s[nt][1]));
            *(float2*)&Pw[(gid + 8) * PS_STRIDE + c] =
                make_float2(to_tf32(s[nt][2]), to_tf32(s[nt][3]));
        }
        __syncwarp();

        // ---- O += P @ V : P A-frags via ldmatrix, V scalar ----
#pragma unroll
        for (int kc = 0; kc < 8; kc++) {
            uint32_t a0, a1, a2, a3;
            LDMATRIX_X4(a0, a1, a2, a3, pw_u + kc * 32);
            float pa[4] = {__uint_as_float(a0), __uint_as_float(a1),
                           __uint_as_float(a2), __uint_as_float(a3)};
            float bv0[8], bv1[8];
            const int vr0 = (kc * 8 + tig) * V_STRIDE;
            const int vr1 = (kc * 8 + tig + 4) * V_STRIDE;
#pragma unroll
            for (int nt = 0; nt < 8; nt++) {
                bv0[nt] = VsC[vr0 + nt * 8 + gid];
                bv1[nt] = VsC[vr1 + nt * 8 + gid];
            }
#pragma unroll
            for (int nt = 0; nt < 8; nt++)
                mma_tf32(o_acc[nt], pa, bv0[nt], bv1[nt]);
        }

        __syncthreads();
        if (kt + 2 < 16) LOAD_KV(kt + 2, kt & 1);
    }

    const float inv0 = 1.0f / l0r;
    const float inv1 = 1.0f / l1r;
    const int r0 = q0 + wid * 16 + gid;
#pragma unroll
    for (int nt = 0; nt < 8; nt++) {
        const int c = nt * 8 + 2 * tig;
        *(float2*)&O[base + (size_t)r0 * D_MODEL + c] =
            make_float2(to_tf32(o_acc[nt][0] * inv0), to_tf32(o_acc[nt][1] * inv0));
        *(float2*)&O[base + (size_t)(r0 + 8) * D_MODEL + c] =
            make_float2(to_tf32(o_acc[nt][2] * inv1), to_tf32(o_acc[nt][3] * inv1));
    }
#undef LOAD_KV
}

// ---------------------------------------------------------------------------
extern "C" void kernel_launch(void* const* d_in, const int* in_sizes, int n_in,
                              void* d_out, int out_size) {
    (void)in_sizes; (void)n_in; (void)out_size;
    const float* x  = (const float*)d_in[0];
    const float* Wq = (const float*)d_in[1];
    const float* bq = (const float*)d_in[2];
    const float* Wk = (const float*)d_in[3];
    const float* bk = (const float*)d_in[4];
    const float* Wv = (const float*)d_in[5];
    const float* bv = (const float*)d_in[6];
    const float* Wo = (const float*)d_in[7];
    const float* bo = (const float*)d_in[8];
    float* out = (float*)d_out;

    float *q, *k, *v, *attn, *xr, *wqr, *wkr, *wvr, *wor;
    cudaGetSymbolAddress((void**)&q, g_q);
    cudaGetSymbolAddress((void**)&k, g_k);
    cudaGetSymbolAddress((void**)&v, g_v);
    cudaGetSymbolAddress((void**)&attn, g_attn);
    cudaGetSymbolAddress((void**)&xr, g_xr);
    cudaGetSymbolAddress((void**)&wqr, g_wqr);
    cudaGetSymbolAddress((void**)&wkr, g_wkr);
    cudaGetSymbolAddress((void**)&wvr, g_wvr);
    cudaGetSymbolAddress((void**)&wor, g_wor);

    const int smem_gemm = GSTG * (AS_SZ + BS_SZ) * (int)sizeof(float); // 107520
    cudaFuncSetAttribute(mma_gemm_kernel<0>,
                         cudaFuncAttributeMaxDynamicSharedMemorySize, smem_gemm);
    cudaFuncSetAttribute(mma_gemm_kernel<1>,
                         cudaFuncAttributeMaxDynamicSharedMemorySize, smem_gemm);
    const int smem_attn =
        (2 * KBUF + 2 * VBUF + 128 * PS_STRIDE) * (int)sizeof(float); // 110592
    cudaFuncSetAttribute(attention_kernel,
                         cudaFuncAttributeMaxDynamicSharedMemorySize, smem_attn);

    // Pre-round x + weights to tf32 (cp.async copies raw bytes; HW truncation
    // of pre-rounded values is exact).
    const int xn4 = TOK * D_MODEL / 4;
    const int wn4 = D_MODEL * D_MODEL / 4;
    round_tf32_kernel<<<(xn4 + 255) / 256, 256>>>(x, xr, xn4);
    round_tf32_kernel<<<(wn4 + 255) / 256, 256>>>(Wq, wqr, wn4);
    round_tf32_kernel<<<(wn4 + 255) / 256, 256>>>(Wk, wkr, wn4);
    round_tf32_kernel<<<(wn4 + 255) / 256, 256>>>(Wv, wvr, wn4);
    round_tf32_kernel<<<(wn4 + 255) / 256, 256>>>(Wo, wor, wn4);

    // Fused QKV projection: one launch, blockIdx.z selects Q/K/V
    dim3 qkv_grid(D_MODEL / 128, TOK / 128, 3);   // (6, 64, 3)
    mma_gemm_kernel<1><<<qkv_grid, 128, smem_gemm>>>(
        xr, wqr, bq, q, wkr, bk, k, wvr, bv, v);

    // Tensor-core flash attention (2 CTAs/SM)
    dim3 attn_grid(SEQ / 128, BATCH * NH);        // (8, 96)
    attention_kernel<<<attn_grid, 256, smem_attn>>>(q, k, v, attn);

    // Output projection (full fp32 output)
    dim3 gemm_grid(D_MODEL / 128, TOK / 128);     // (6, 64)
    mma_gemm_kernel<0><<<gemm_grid, 128, smem_gemm>>>(
        attn, wor, bo, out, nullptr, nullptr, nullptr, nullptr, nullptr, nullptr);
}

// round 14
// speedup vs baseline: 1.8597x; 1.0112x over previous
#include <cuda_runtime.h>
#include <math.h>
#include <cstdint>

#define D_MODEL 768
#define NH      12
#define DHEAD   64
#define BATCH   8
#define SEQ     1024
#define TOK     (BATCH * SEQ)   // 8192

// Scratch (device globals — no runtime allocation allowed)
__device__ float g_q[TOK * D_MODEL];
__device__ float g_k[TOK * D_MODEL];
__device__ float g_v[TOK * D_MODEL];
__device__ float g_attn[TOK * D_MODEL];
__device__ float g_xr[TOK * D_MODEL];        // x rounded to tf32
__device__ float g_wqr[D_MODEL * D_MODEL];   // weights rounded to tf32
__device__ float g_wkr[D_MODEL * D_MODEL];
__device__ float g_wvr[D_MODEL * D_MODEL];
__device__ float g_wor[D_MODEL * D_MODEL];

__device__ __forceinline__ float to_tf32(float x) {
    float r;
    asm("cvt.rna.tf32.f32 %0, %1;" : "=f"(r) : "f"(x));
    return r;
}

__device__ __forceinline__ uint32_t smem_u32(const void* p) {
    uint32_t a;
    asm("{ .reg .u64 t; cvta.to.shared.u64 t, %1; cvt.u32.u64 %0, t; }"
        : "=r"(a) : "l"(p));
    return a;
}

// c += a @ b  (m16n8k8 tf32, fp32 accum)
__device__ __forceinline__ void mma_tf32(float* c, const float* a, float b0, float b1) {
    asm volatile(
        "mma.sync.aligned.m16n8k8.row.col.f32.tf32.tf32.f32 "
        "{%0,%1,%2,%3}, {%4,%5,%6,%7}, {%8,%9}, {%0,%1,%2,%3};"
        : "+f"(c[0]), "+f"(c[1]), "+f"(c[2]), "+f"(c[3])
        : "r"(__float_as_uint(a[0])), "r"(__float_as_uint(a[1])),
          "r"(__float_as_uint(a[2])), "r"(__float_as_uint(a[3])),
          "r"(__float_as_uint(b0)), "r"(__float_as_uint(b1)));
}

#define LDMATRIX_X4(r0, r1, r2, r3, addr)                                     \
    asm volatile("ldmatrix.sync.aligned.m8n8.x4.shared.b16 {%0,%1,%2,%3}, [%4];" \
                 : "=r"(r0), "=r"(r1), "=r"(r2), "=r"(r3) : "r"(addr))

#define CP_ASYNC16(saddr, gptr) \
    asm volatile("cp.async.cg.shared.global [%0], [%1], 16;" \
                 :: "r"(saddr), "l"(gptr) : "memory")
#define CP_COMMIT() asm volatile("cp.async.commit_group;" ::: "memory")
#define CP_WAIT(n)  asm volatile("cp.async.wait_group %0;" :: "n"(n) : "memory")

// ===========================================================================
// Fused tf32 pre-rounding: ONE launch rounds x + all 4 weight matrices.
// blockIdx.y selects the array; oversized rows exit on the guard.
// ===========================================================================
#define XN4 (TOK * D_MODEL / 4)        // 1572864
#define WN4 (D_MODEL * D_MODEL / 4)    // 147456

__global__ void __launch_bounds__(256)
round_all_kernel(const float* __restrict__ x,  float* __restrict__ xr,
                 const float* __restrict__ wq, float* __restrict__ wqr,
                 const float* __restrict__ wk, float* __restrict__ wkr,
                 const float* __restrict__ wv, float* __restrict__ wvr,
                 const float* __restrict__ wo, float* __restrict__ wor) {
    const int y = blockIdx.y;
    const float* src;
    float* dst;
    int n4;
    if (y == 0)      { src = x;  dst = xr;  n4 = XN4; }
    else if (y == 1) { src = wq; dst = wqr; n4 = WN4; }
    else if (y == 2) { src = wk; dst = wkr; n4 = WN4; }
    else if (y == 3) { src = wv; dst = wvr; n4 = WN4; }
    else             { src = wo; dst = wor; n4 = WN4; }

    const int i = blockIdx.x * blockDim.x + threadIdx.x;
    if (i < n4) {
        float4 v = ((const float4*)src)[i];
        v.x = to_tf32(v.x); v.y = to_tf32(v.y);
        v.z = to_tf32(v.z); v.w = to_tf32(v.w);
        ((float4*)dst)[i] = v;
    }
}

// ===========================================================================
// tf32 tensor-core GEMM + bias, v2.1.
// CTA tile 128x128, 128 threads = 4 warps (2x2), warp tile 64x64.
// 3-stage cp.async pipeline, ONE barrier per iteration.
// A-fragments via ldmatrix.x4 (f32-as-2xb16; conflict-free @ AS_STRIDE=36).
// ===========================================================================
#define BK  32
#define NIT (D_MODEL / BK)   // 24
#define AS_STRIDE 36
#define BS_STRIDE 136
#define AS_SZ (128 * AS_STRIDE)
#define BS_SZ (BK * BS_STRIDE)
#define GSTG 3

template <int QKV>
__global__ void __launch_bounds__(128, 2)
mma_gemm_kernel(const float* __restrict__ A,
                const float* __restrict__ B0, const float* __restrict__ bias0,
                float* __restrict__ C0,
                const float* __restrict__ B1, const float* __restrict__ bias1,
                float* __restrict__ C1,
                const float* __restrict__ B2, const float* __restrict__ bias2,
                float* __restrict__ C2) {
    extern __shared__ float gsm[];
    float* As_f = gsm;
    float* Bs_f = gsm + GSTG * AS_SZ;

    const float* B    = B0;
    const float* bias = bias0;
    float*       C    = C0;
    if (QKV) {
        if (blockIdx.z == 1) { B = B1; bias = bias1; C = C1; }
        else if (blockIdx.z == 2) { B = B2; bias = bias2; C = C2; }
    }

    const int tid = threadIdx.x;
    const int lane = tid & 31;
    const int wid = tid >> 5;
    const int gid = lane >> 2;
    const int tig = lane & 3;
    const int warp_m = wid & 1;
    const int warp_n = wid >> 1;
    const int m0 = blockIdx.y * 128;
    const int n0 = blockIdx.x * 128;

    const uint32_t as_b = smem_u32(As_f);
    const uint32_t bs_b = smem_u32(Bs_f);

    // ldmatrix per-lane offset for A fragments (in floats):
    // matrix row = lane&15 (within the 16-row block), col half = (lane>>4)*4
    const int a_lm = (lane & 15) * AS_STRIDE + (lane >> 4) * 4;

    const int a_col = (tid & 7) * 4;
    const int b_c   = (tid & 31) * 4;
    const float* aptr[8];
    const float* bptr[8];
    uint32_t a_dst[8], b_dst[8];
#pragma unroll
    for (int i = 0; i < 8; i++) {
        const int ar = (tid + i * 128) >> 3;
        const int bkr = (tid + i * 128) >> 5;
        aptr[i] = A + (size_t)(m0 + ar) * D_MODEL + a_col;
        a_dst[i] = as_b + (ar * AS_STRIDE + a_col) * 4;
        b_dst[i] = bs_b + (bkr * BS_STRIDE + b_c) * 4;
        if (QKV == 0) {
            bptr[i] = B + (size_t)bkr * D_MODEL + n0 + b_c;
        } else {
            const int c = n0 + b_c;
            bptr[i] = B + ((size_t)(c >> 6) * D_MODEL + bkr) * DHEAD + (c & 63);
        }
    }
    const int b_adv = (QKV == 0) ? BK * D_MODEL : BK * DHEAD;

#define LOAD_STAGE(koff_a, koff_b, st)                                        \
    do {                                                                      \
        _Pragma("unroll")                                                     \
        for (int i = 0; i < 8; i++)                                           \
            CP_ASYNC16(a_dst[i] + (st) * (AS_SZ * 4), aptr[i] + (koff_a));    \
        _Pragma("unroll")                                                     \
        for (int i = 0; i < 8; i++)                                           \
            CP_ASYNC16(b_dst[i] + (st) * (BS_SZ * 4), bptr[i] + (koff_b));    \
        CP_COMMIT();                                                          \
    } while (0)

    float acc[4][8][4];
#pragma unroll
    for (int mt = 0; mt < 4; mt++)
#pragma unroll
        for (int nt = 0; nt < 8; nt++)
#pragma unroll
            for (int i = 0; i < 4; i++) acc[mt][nt][i] = 0.0f;

    LOAD_STAGE(0, 0, 0);
    LOAD_STAGE(BK, b_adv, 1);

    int st = 0;
#pragma unroll 1
    for (int it = 0; it < NIT; it++) {
        CP_WAIT(1);
        __syncthreads();

        const int st2 = (st + 2 >= GSTG) ? st + 2 - GSTG : st + 2;
        if (it + 2 < NIT) {
            LOAD_STAGE((it + 2) * BK, (it + 2) * b_adv, st2);
        } else {
            CP_COMMIT();
        }

        const uint32_t asr_u = as_b + st * (AS_SZ * 4)
                             + (warp_m * 64 * AS_STRIDE + a_lm) * 4;
        const float* Bsr = Bs_f + st * BS_SZ;

#pragma unroll
        for (int ks = 0; ks < 4; ks++) {
            const int kb = ks * 8;
            float a[4][4];
#pragma unroll
            for (int mt = 0; mt < 4; mt++) {
                uint32_t r0, r1, r2, r3;
                LDMATRIX_X4(r0, r1, r2, r3,
                            asr_u + (mt * 16 * AS_STRIDE + kb) * 4);
                a[mt][0] = __uint_as_float(r0);
                a[mt][1] = __uint_as_float(r1);
                a[mt][2] = __uint_as_float(r2);
                a[mt][3] = __uint_as_float(r3);
            }
            float b[8][2];
#pragma unroll
            for (int nt = 0; nt < 8; nt++) {
                const int cn = warp_n * 64 + nt * 8 + gid;
                b[nt][0] = Bsr[(kb + tig) * BS_STRIDE + cn];
                b[nt][1] = Bsr[(kb + tig + 4) * BS_STRIDE + cn];
            }
#pragma unroll
            for (int mt = 0; mt < 4; mt++)
#pragma unroll
                for (int nt = 0; nt < 8; nt++)
                    mma_tf32(acc[mt][nt], a[mt], b[nt][0], b[nt][1]);
        }

        st = (st + 1 >= GSTG) ? 0 : st + 1;
    }

#pragma unroll
    for (int nt = 0; nt < 8; nt++) {
        const int cn = n0 + warp_n * 64 + nt * 8 + 2 * tig;
        const float2 bb = *(const float2*)&bias[cn];
#pragma unroll
        for (int mt = 0; mt < 4; mt++) {
            const int r = m0 + warp_m * 64 + mt * 16 + gid;
            float2 v0 = make_float2(acc[mt][nt][0] + bb.x, acc[mt][nt][1] + bb.y);
            float2 v1 = make_float2(acc[mt][nt][2] + bb.x, acc[mt][nt][3] + bb.y);
            if (QKV) {
                v0.x = to_tf32(v0.x); v0.y = to_tf32(v0.y);
                v1.x = to_tf32(v1.x); v1.y = to_tf32(v1.y);
            }
            *(float2*)&C[(size_t)r * D_MODEL + cn] = v0;
            *(float2*)&C[(size_t)(r + 8) * D_MODEL + cn] = v1;
        }
    }
#undef LOAD_STAGE
}

// ===========================================================================
// Tensor-core flash attention (tf32 mma.sync) — v3 (UNCHANGED from R12):
//  * K B-fragments via ldmatrix.x4, P A-fragments via ldmatrix.x4
//  * softmax in base-2 (Q pre-scaled by 0.125*log2 e)
// ===========================================================================
#define K_STRIDE 68
#define V_STRIDE 72
#define PS_STRIDE 76
#define KBUF     (64 * K_STRIDE)
#define VBUF     (64 * V_STRIDE)
#define QSCALE   0.18033688011112042f   // 0.125 * log2(e)

__global__ void __launch_bounds__(256, 2)
attention_kernel(const float* __restrict__ Q, const float* __restrict__ K,
                 const float* __restrict__ V, float* __restrict__ O) {
    extern __shared__ float smem[];
    float* Ks = smem;                    // [2][64][K_STRIDE]
    float* Vs = Ks + 2 * KBUF;           // [2][64][V_STRIDE]
    float* Ps = Vs + 2 * VBUF;           // [128][PS_STRIDE]  (also Q staging)

    const int tid = threadIdx.x;
    const int lane = tid & 31;
    const int wid = tid >> 5;
    const int gid = lane >> 2;
    const int tig = lane & 3;
    const int b = blockIdx.y / NH;
    const int h = blockIdx.y % NH;
    const size_t base = (size_t)b * SEQ * D_MODEL + (size_t)h * DHEAD;
    const int q0 = blockIdx.x * 128;

    const uint32_t smem_b = smem_u32(smem);
    const uint32_t ks_b = smem_b;
    const uint32_t vs_b = smem_b + 2 * KBUF * 4;
    const uint32_t ps_b = smem_b + (2 * KBUF + 2 * VBUF) * 4;

    const int k_lm = (((lane >> 4) & 1) * 8 + (lane & 7)) * K_STRIDE
                   + ((lane >> 3) & 1) * 4;
    const int p_lm = ((lane & 7) + ((lane >> 3) & 1) * 8) * PS_STRIDE
                   + ((lane >> 4) & 1) * 4;

#pragma unroll
    for (int i = 0; i < 8; i++) {
        const int id = tid + i * 256;
        const int r = id >> 4, c4 = (id & 15) * 4;
        CP_ASYNC16(ps_b + (r * PS_STRIDE + c4) * 4,
                   Q + base + (size_t)(q0 + r) * D_MODEL + c4);
    }
    CP_COMMIT();

#define LOAD_KV(kt, buf)                                                      \
    do {                                                                      \
        _Pragma("unroll")                                                     \
        for (int i = 0; i < 4; i++) {                                         \
            const int id = tid + i * 256;                                     \
            const int r = id >> 4, c4 = (id & 15) * 4;                        \
            const size_t go = base + (size_t)((kt) * 64 + r) * D_MODEL + c4;  \
            CP_ASYNC16(ks_b + ((buf) * KBUF + r * K_STRIDE + c4) * 4, K + go); \
            CP_ASYNC16(vs_b + ((buf) * VBUF + r * V_STRIDE + c4) * 4, V + go); \
        }                                                                     \
        CP_COMMIT();                                                          \
    } while (0)

    LOAD_KV(0, 0);
    LOAD_KV(1, 1);

    CP_WAIT(2);
    __syncthreads();

    float qf[8][4];
    {
        const int r0 = (wid * 16 + gid) * PS_STRIDE;
        const int r1 = (wid * 16 + gid + 8) * PS_STRIDE;
#pragma unroll
        for (int kc = 0; kc < 8; kc++) {
            const int c = kc * 8 + tig;
            qf[kc][0] = to_tf32(QSCALE * Ps[r0 + c]);
            qf[kc][1] = to_tf32(QSCALE * Ps[r1 + c]);
            qf[kc][2] = to_tf32(QSCALE * Ps[r0 + c + 4]);
            qf[kc][3] = to_tf32(QSCALE * Ps[r1 + c + 4]);
        }
    }
    __syncthreads();

    float o_acc[8][4];
#pragma unroll
    for (int nt = 0; nt < 8; nt++)
#pragma unroll
        for (int i = 0; i < 4; i++) o_acc[nt][i] = 0.0f;
    float m0r = -1e30f, m1r = -1e30f, l0r = 0.0f, l1r = 0.0f;

    float* Pw = Ps + wid * 16 * PS_STRIDE;
    const uint32_t pw_u = ps_b + (wid * 16 * PS_STRIDE + p_lm) * 4;

#pragma unroll 1
    for (int kt = 0; kt < 16; kt++) {
        if (kt < 15) { CP_WAIT(1); } else { CP_WAIT(0); }
        __syncthreads();
        const uint32_t ksc_u = ks_b + ((kt & 1) * KBUF + k_lm) * 4;
        const float* VsC = Vs + (kt & 1) * VBUF;

        float s[8][4];
#pragma unroll
        for (int nt = 0; nt < 8; nt++)
#pragma unroll
            for (int i = 0; i < 4; i++) s[nt][i] = 0.0f;

#pragma unroll
        for (int kc = 0; kc < 8; kc++) {
#pragma unroll
            for (int p = 0; p < 4; p++) {
                uint32_t r0, r1, r2, r3;
                LDMATRIX_X4(r0, r1, r2, r3,
                            ksc_u + (16 * p * K_STRIDE + kc * 8) * 4);
                mma_tf32(s[2 * p], qf[kc],
                         __uint_as_float(r0), __uint_as_float(r1));
                mma_tf32(s[2 * p + 1], qf[kc],
                         __uint_as_float(r2), __uint_as_float(r3));
            }
        }

        float mx0 = s[0][0], mx1 = s[0][2];
#pragma unroll
        for (int nt = 0; nt < 8; nt++) {
            mx0 = fmaxf(mx0, fmaxf(s[nt][0], s[nt][1]));
            mx1 = fmaxf(mx1, fmaxf(s[nt][2], s[nt][3]));
        }
        mx0 = fmaxf(mx0, __shfl_xor_sync(0xffffffffu, mx0, 1));
        mx0 = fmaxf(mx0, __shfl_xor_sync(0xffffffffu, mx0, 2));
        mx1 = fmaxf(mx1, __shfl_xor_sync(0xffffffffu, mx1, 1));
        mx1 = fmaxf(mx1, __shfl_xor_sync(0xffffffffu, mx1, 2));

        const float nm0 = fmaxf(m0r, mx0);
        const float nm1 = fmaxf(m1r, mx1);
        const float fac0 = exp2f(m0r - nm0);
        const float fac1 = exp2f(m1r - nm1);
        m0r = nm0; m1r = nm1;

        float sum0 = 0.0f, sum1 = 0.0f;
#pragma unroll
        for (int nt = 0; nt < 8; nt++) {
            s[nt][0] = exp2f(s[nt][0] - nm0);
            s[nt][1] = exp2f(s[nt][1] - nm0);
            s[nt][2] = exp2f(s[nt][2] - nm1);
            s[nt][3] = exp2f(s[nt][3] - nm1);
            sum0 += s[nt][0] + s[nt][1];
            sum1 += s[nt][2] + s[nt][3];
        }
        sum0 += __shfl_xor_sync(0xffffffffu, sum0, 1);
        sum0 += __shfl_xor_sync(0xffffffffu, sum0, 2);
        sum1 += __shfl_xor_sync(0xffffffffu, sum1, 1);
        sum1 += __shfl_xor_sync(0xffffffffu, sum1, 2);
        l0r = l0r * fac0 + sum0;
        l1r = l1r * fac1 + sum1;

#pragma unroll
        for (int nt = 0; nt < 8; nt++) {
            o_acc[nt][0] *= fac0; o_acc[nt][1] *= fac0;
            o_acc[nt][2] *= fac1; o_acc[nt][3] *= fac1;
        }

#pragma unroll
        for (int nt = 0; nt < 8; nt++) {
            const int c = nt * 8 + 2 * tig;
            *(float2*)&Pw[gid * PS_STRIDE + c] =
                make_float2(to_tf32(s[nt][0]), to_tf32(s[nt][1]));
            *(float2*)&Pw[(gid + 8) * PS_STRIDE + c] =
                make_float2(to_tf32(s[nt][2]), to_tf32(s[nt][3]));
        }
        __syncwarp();

#pragma unroll
        for (int kc = 0; kc < 8; kc++) {
            uint32_t a0, a1, a2, a3;
            LDMATRIX_X4(a0, a1, a2, a3, pw_u + kc * 32);
            float pa[4] = {__uint_as_float(a0), __uint_as_float(a1),
                           __uint_as_float(a2), __uint_as_float(a3)};
            float bv0[8], bv1[8];
            const int vr0 = (kc * 8 + tig) * V_STRIDE;
            const int vr1 = (kc * 8 + tig + 4) * V_STRIDE;
#pragma unroll
            for (int nt = 0; nt < 8; nt++) {
                bv0[nt] = VsC[vr0 + nt * 8 + gid];
                bv1[nt] = VsC[vr1 + nt * 8 + gid];
            }
#pragma unroll
            for (int nt = 0; nt < 8; nt++)
                mma_tf32(o_acc[nt], pa, bv0[nt], bv1[nt]);
        }

        __syncthreads();
        if (kt + 2 < 16) LOAD_KV(kt + 2, kt & 1);
    }

    const float inv0 = 1.0f / l0r;
    const float inv1 = 1.0f / l1r;
    const int r0 = q0 + wid * 16 + gid;
#pragma unroll
    for (int nt = 0; nt < 8; nt++) {
        const int c = nt * 8 + 2 * tig;
        *(float2*)&O[base + (size_t)r0 * D_MODEL + c] =
            make_float2(to_tf32(o_acc[nt][0] * inv0), to_tf32(o_acc[nt][1] * inv0));
        *(float2*)&O[base + (size_t)(r0 + 8) * D_MODEL + c] =
            make_float2(to_tf32(o_acc[nt][2] * inv1), to_tf32(o_acc[nt][3] * inv1));
    }
#undef LOAD_KV
}

// ---------------------------------------------------------------------------
extern "C" void kernel_launch(void* const* d_in, const int* in_sizes, int n_in,
                              void* d_out, int out_size) {
    (void)in_sizes; (void)n_in; (void)out_size;
    const float* x  = (const float*)d_in[0];
    const float* Wq = (const float*)d_in[1];
    const float* bq = (const float*)d_in[2];
    const float* Wk = (const float*)d_in[3];
    const float* bk = (const float*)d_in[4];
    const float* Wv = (const float*)d_in[5];
    const float* bv = (const float*)d_in[6];
    const float* Wo = (const float*)d_in[7];
    const float* bo = (const float*)d_in[8];
    float* out = (float*)d_out;

    float *q, *k, *v, *attn, *xr, *wqr, *wkr, *wvr, *wor;
    cudaGetSymbolAddress((void**)&q, g_q);
    cudaGetSymbolAddress((void**)&k, g_k);
    cudaGetSymbolAddress((void**)&v, g_v);
    cudaGetSymbolAddress((void**)&attn, g_attn);
    cudaGetSymbolAddress((void**)&xr, g_xr);
    cudaGetSymbolAddress((void**)&wqr, g_wqr);
    cudaGetSymbolAddress((void**)&wkr, g_wkr);
    cudaGetSymbolAddress((void**)&wvr, g_wvr);
    cudaGetSymbolAddress((void**)&wor, g_wor);

    const int smem_gemm = GSTG * (AS_SZ + BS_SZ) * (int)sizeof(float); // 107520
    cudaFuncSetAttribute(mma_gemm_kernel<0>,
                         cudaFuncAttributeMaxDynamicSharedMemorySize, smem_gemm);
    cudaFuncSetAttribute(mma_gemm_kernel<1>,
                         cudaFuncAttributeMaxDynamicSharedMemorySize, smem_gemm);
    const int smem_attn =
        (2 * KBUF + 2 * VBUF + 128 * PS_STRIDE) * (int)sizeof(float); // 110592
    cudaFuncSetAttribute(attention_kernel,
                         cudaFuncAttributeMaxDynamicSharedMemorySize, smem_attn);

    // ONE fused pre-rounding launch (x + 4 weights -> tf32)
    dim3 round_grid((XN4 + 255) / 256, 5);
    round_all_kernel<<<round_grid, 256>>>(x, xr, Wq, wqr, Wk, wkr, Wv, wvr, Wo, wor);

    // Fused QKV projection: one launch, blockIdx.z selects Q/K/V
    dim3 qkv_grid(D_MODEL / 128, TOK / 128, 3);   // (6, 64, 3)
    mma_gemm_kernel<1><<<qkv_grid, 128, smem_gemm>>>(
        xr, wqr, bq, q, wkr, bk, k, wvr, bv, v);

    // Tensor-core flash attention (2 CTAs/SM)
    dim3 attn_grid(SEQ / 128, BATCH * NH);        // (8, 96)
    attention_kernel<<<attn_grid, 256, smem_attn>>>(q, k, v, attn);

    // Output projection (full fp32 output)
    dim3 gemm_grid(D_MODEL / 128, TOK / 128);     // (6, 64)
    mma_gemm_kernel<0><<<gemm_grid, 128, smem_gemm>>>(
        attn, wor, bo, out, nullptr, nullptr, nullptr, nullptr, nullptr, nullptr);
}

// round 15
// speedup vs baseline: 1.8854x; 1.0138x over previous
#include <cuda_runtime.h>
#include <math.h>
#include <cstdint>

#define D_MODEL 768
#define NH      12
#define DHEAD   64
#define BATCH   8
#define SEQ     1024
#define TOK     (BATCH * SEQ)   // 8192

// Scratch (device globals — no runtime allocation allowed)
__device__ float g_q[TOK * D_MODEL];
__device__ float g_k[TOK * D_MODEL];
__device__ float g_v[TOK * D_MODEL];
__device__ float g_attn[TOK * D_MODEL];
__device__ float g_xr[TOK * D_MODEL];        // x rounded to tf32
__device__ float g_wqr[D_MODEL * D_MODEL];   // weights rounded to tf32
__device__ float g_wkr[D_MODEL * D_MODEL];
__device__ float g_wvr[D_MODEL * D_MODEL];
__device__ float g_wor[D_MODEL * D_MODEL];

__device__ __forceinline__ float to_tf32(float x) {
    float r;
    asm("cvt.rna.tf32.f32 %0, %1;" : "=f"(r) : "f"(x));
    return r;
}

__device__ __forceinline__ uint32_t smem_u32(const void* p) {
    uint32_t a;
    asm("{ .reg .u64 t; cvta.to.shared.u64 t, %1; cvt.u32.u64 %0, t; }"
        : "=r"(a) : "l"(p));
    return a;
}

// c += a @ b  (m16n8k8 tf32, fp32 accum)
__device__ __forceinline__ void mma_tf32(float* c, const float* a, float b0, float b1) {
    asm volatile(
        "mma.sync.aligned.m16n8k8.row.col.f32.tf32.tf32.f32 "
        "{%0,%1,%2,%3}, {%4,%5,%6,%7}, {%8,%9}, {%0,%1,%2,%3};"
        : "+f"(c[0]), "+f"(c[1]), "+f"(c[2]), "+f"(c[3])
        : "r"(__float_as_uint(a[0])), "r"(__float_as_uint(a[1])),
          "r"(__float_as_uint(a[2])), "r"(__float_as_uint(a[3])),
          "r"(__float_as_uint(b0)), "r"(__float_as_uint(b1)));
}

#define LDMATRIX_X4(r0, r1, r2, r3, addr)                                     \
    asm volatile("ldmatrix.sync.aligned.m8n8.x4.shared.b16 {%0,%1,%2,%3}, [%4];" \
                 : "=r"(r0), "=r"(r1), "=r"(r2), "=r"(r3) : "r"(addr))

#define CP_ASYNC16(saddr, gptr) \
    asm volatile("cp.async.cg.shared.global [%0], [%1], 16;" \
                 :: "r"(saddr), "l"(gptr) : "memory")
#define CP_COMMIT() asm volatile("cp.async.commit_group;" ::: "memory")
#define CP_WAIT(n)  asm volatile("cp.async.wait_group %0;" :: "n"(n) : "memory")

// ===========================================================================
// Fused tf32 pre-rounding: ONE launch rounds x + all 4 weight matrices.
// ===========================================================================
#define XN4 (TOK * D_MODEL / 4)        // 1572864
#define WN4 (D_MODEL * D_MODEL / 4)    // 147456

__global__ void __launch_bounds__(256)
round_all_kernel(const float* __restrict__ x,  float* __restrict__ xr,
                 const float* __restrict__ wq, float* __restrict__ wqr,
                 const float* __restrict__ wk, float* __restrict__ wkr,
                 const float* __restrict__ wv, float* __restrict__ wvr,
                 const float* __restrict__ wo, float* __restrict__ wor) {
    const int y = blockIdx.y;
    const float* src;
    float* dst;
    int n4;
    if (y == 0)      { src = x;  dst = xr;  n4 = XN4; }
    else if (y == 1) { src = wq; dst = wqr; n4 = WN4; }
    else if (y == 2) { src = wk; dst = wkr; n4 = WN4; }
    else if (y == 3) { src = wv; dst = wvr; n4 = WN4; }
    else             { src = wo; dst = wor; n4 = WN4; }

    const int i = blockIdx.x * blockDim.x + threadIdx.x;
    if (i < n4) {
        float4 v = ((const float4*)src)[i];
        v.x = to_tf32(v.x); v.y = to_tf32(v.y);
        v.z = to_tf32(v.z); v.w = to_tf32(v.w);
        ((float4*)dst)[i] = v;
    }
}

// ===========================================================================
// tf32 tensor-core GEMM + bias, v3.
// CTA tile 128x128, 256 threads = 8 warps (2 m-bands x 4 n-bands),
// warp tile 64x32 -> 4 warps/SMSP at 2 CTAs/SM (latency hiding).
// 3-stage cp.async pipeline, ONE barrier per iteration.
// A-fragments via ldmatrix.x4; B-fragments scalar (conflict-free).
// ===========================================================================
#define BK  32
#define NIT (D_MODEL / BK)   // 24
#define AS_STRIDE 36
#define BS_STRIDE 136
#define AS_SZ (128 * AS_STRIDE)
#define BS_SZ (BK * BS_STRIDE)
#define GSTG 3

template <int QKV>
__global__ void __launch_bounds__(256, 2)
mma_gemm_kernel(const float* __restrict__ A,
                const float* __restrict__ B0, const float* __restrict__ bias0,
                float* __restrict__ C0,
                const float* __restrict__ B1, const float* __restrict__ bias1,
                float* __restrict__ C1,
                const float* __restrict__ B2, const float* __restrict__ bias2,
                float* __restrict__ C2) {
    extern __shared__ float gsm[];
    float* As_f = gsm;
    float* Bs_f = gsm + GSTG * AS_SZ;

    const float* B    = B0;
    const float* bias = bias0;
    float*       C    = C0;
    if (QKV) {
        if (blockIdx.z == 1) { B = B1; bias = bias1; C = C1; }
        else if (blockIdx.z == 2) { B = B2; bias = bias2; C = C2; }
    }

    const int tid = threadIdx.x;
    const int lane = tid & 31;
    const int wid = tid >> 5;
    const int gid = lane >> 2;
    const int tig = lane & 3;
    const int warp_m = wid & 1;    // 2 bands x 64 rows
    const int warp_n = wid >> 1;   // 4 bands x 32 cols
    const int m0 = blockIdx.y * 128;
    const int n0 = blockIdx.x * 128;

    const uint32_t as_b = smem_u32(As_f);
    const uint32_t bs_b = smem_u32(Bs_f);

    // ldmatrix per-lane offset for A fragments (in floats)
    const int a_lm = (lane & 15) * AS_STRIDE + (lane >> 4) * 4;

    // Loaders: A tile 1024 float4, 4/thread (row=id>>3); B tile 1024 float4,
    // 4/thread (krow=id>>5).
    const int a_col = (tid & 7) * 4;
    const int b_c   = (tid & 31) * 4;
    const float* aptr[4];
    const float* bptr[4];
    uint32_t a_dst[4], b_dst[4];
#pragma unroll
    for (int i = 0; i < 4; i++) {
        const int ar = (tid + i * 256) >> 3;
        const int bkr = (tid + i * 256) >> 5;
        aptr[i] = A + (size_t)(m0 + ar) * D_MODEL + a_col;
        a_dst[i] = as_b + (ar * AS_STRIDE + a_col) * 4;
        b_dst[i] = bs_b + (bkr * BS_STRIDE + b_c) * 4;
        if (QKV == 0) {
            bptr[i] = B + (size_t)bkr * D_MODEL + n0 + b_c;
        } else {
            const int c = n0 + b_c;
            bptr[i] = B + ((size_t)(c >> 6) * D_MODEL + bkr) * DHEAD + (c & 63);
        }
    }
    const int b_adv = (QKV == 0) ? BK * D_MODEL : BK * DHEAD;

#define LOAD_STAGE(koff_a, koff_b, st)                                        \
    do {                                                                      \
        _Pragma("unroll")                                                     \
        for (int i = 0; i < 4; i++)                                           \
            CP_ASYNC16(a_dst[i] + (st) * (AS_SZ * 4), aptr[i] + (koff_a));    \
        _Pragma("unroll")                                                     \
        for (int i = 0; i < 4; i++)                                           \
            CP_ASYNC16(b_dst[i] + (st) * (BS_SZ * 4), bptr[i] + (koff_b));    \
        CP_COMMIT();                                                          \
    } while (0)

    float acc[4][4][4];
#pragma unroll
    for (int mt = 0; mt < 4; mt++)
#pragma unroll
        for (int nt = 0; nt < 4; nt++)
#pragma unroll
            for (int i = 0; i < 4; i++) acc[mt][nt][i] = 0.0f;

    LOAD_STAGE(0, 0, 0);
    LOAD_STAGE(BK, b_adv, 1);

    int st = 0;
#pragma unroll 1
    for (int it = 0; it < NIT; it++) {
        CP_WAIT(1);
        __syncthreads();

        const int st2 = (st + 2 >= GSTG) ? st + 2 - GSTG : st + 2;
        if (it + 2 < NIT) {
            LOAD_STAGE((it + 2) * BK, (it + 2) * b_adv, st2);
        } else {
            CP_COMMIT();
        }

        const uint32_t asr_u = as_b + st * (AS_SZ * 4)
                             + (warp_m * 64 * AS_STRIDE + a_lm) * 4;
        const float* Bsr = Bs_f + st * BS_SZ;

#pragma unroll
        for (int ks = 0; ks < 4; ks++) {
            const int kb = ks * 8;
            float a[4][4];
#pragma unroll
            for (int mt = 0; mt < 4; mt++) {
                uint32_t r0, r1, r2, r3;
                LDMATRIX_X4(r0, r1, r2, r3,
                            asr_u + (mt * 16 * AS_STRIDE + kb) * 4);
                a[mt][0] = __uint_as_float(r0);
                a[mt][1] = __uint_as_float(r1);
                a[mt][2] = __uint_as_float(r2);
                a[mt][3] = __uint_as_float(r3);
            }
            float b[4][2];
#pragma unroll
            for (int nt = 0; nt < 4; nt++) {
                const int cn = warp_n * 32 + nt * 8 + gid;
                b[nt][0] = Bsr[(kb + tig) * BS_STRIDE + cn];
                b[nt][1] = Bsr[(kb + tig + 4) * BS_STRIDE + cn];
            }
#pragma unroll
            for (int mt = 0; mt < 4; mt++)
#pragma unroll
                for (int nt = 0; nt < 4; nt++)
                    mma_tf32(acc[mt][nt], a[mt], b[nt][0], b[nt][1]);
        }

        st = (st + 1 >= GSTG) ? 0 : st + 1;
    }

    // ---- epilogue: fragment-direct stores + bias ----
#pragma unroll
    for (int nt = 0; nt < 4; nt++) {
        const int cn = n0 + warp_n * 32 + nt * 8 + 2 * tig;
        const float2 bb = *(const float2*)&bias[cn];
#pragma unroll
        for (int mt = 0; mt < 4; mt++) {
            const int r = m0 + warp_m * 64 + mt * 16 + gid;
            float2 v0 = make_float2(acc[mt][nt][0] + bb.x, acc[mt][nt][1] + bb.y);
            float2 v1 = make_float2(acc[mt][nt][2] + bb.x, acc[mt][nt][3] + bb.y);
            if (QKV) {
                v0.x = to_tf32(v0.x); v0.y = to_tf32(v0.y);
                v1.x = to_tf32(v1.x); v1.y = to_tf32(v1.y);
            }
            *(float2*)&C[(size_t)r * D_MODEL + cn] = v0;
            *(float2*)&C[(size_t)(r + 8) * D_MODEL + cn] = v1;
        }
    }
#undef LOAD_STAGE
}

// ===========================================================================
// Tensor-core flash attention (tf32 mma.sync) — v3 (UNCHANGED from R12/R13):
//  * K B-fragments via ldmatrix.x4, P A-fragments via ldmatrix.x4
//  * softmax in base-2 (Q pre-scaled by 0.125*log2 e)
// ===========================================================================
#define K_STRIDE 68
#define V_STRIDE 72
#define PS_STRIDE 76
#define KBUF     (64 * K_STRIDE)
#define VBUF     (64 * V_STRIDE)
#define QSCALE   0.18033688011112042f   // 0.125 * log2(e)

__global__ void __launch_bounds__(256, 2)
attention_kernel(const float* __restrict__ Q, const float* __restrict__ K,
                 const float* __restrict__ V, float* __restrict__ O) {
    extern __shared__ float smem[];
    float* Ks = smem;                    // [2][64][K_STRIDE]
    float* Vs = Ks + 2 * KBUF;           // [2][64][V_STRIDE]
    float* Ps = Vs + 2 * VBUF;           // [128][PS_STRIDE]  (also Q staging)

    const int tid = threadIdx.x;
    const int lane = tid & 31;
    const int wid = tid >> 5;
    const int gid = lane >> 2;
    const int tig = lane & 3;
    const int b = blockIdx.y / NH;
    const int h = blockIdx.y % NH;
    const size_t base = (size_t)b * SEQ * D_MODEL + (size_t)h * DHEAD;
    const int q0 = blockIdx.x * 128;

    const uint32_t smem_b = smem_u32(smem);
    const uint32_t ks_b = smem_b;
    const uint32_t vs_b = smem_b + 2 * KBUF * 4;
    const uint32_t ps_b = smem_b + (2 * KBUF + 2 * VBUF) * 4;

    const int k_lm = (((lane >> 4) & 1) * 8 + (lane & 7)) * K_STRIDE
                   + ((lane >> 3) & 1) * 4;
    const int p_lm = ((lane & 7) + ((lane >> 3) & 1) * 8) * PS_STRIDE
                   + ((lane >> 4) & 1) * 4;

#pragma unroll
    for (int i = 0; i < 8; i++) {
        const int id = tid + i * 256;
        const int r = id >> 4, c4 = (id & 15) * 4;
        CP_ASYNC16(ps_b + (r * PS_STRIDE + c4) * 4,
                   Q + base + (size_t)(q0 + r) * D_MODEL + c4);
    }
    CP_COMMIT();

#define LOAD_KV(kt, buf)                                                      \
    do {                                                                      \
        _Pragma("unroll")                                                     \
        for (int i = 0; i < 4; i++) {                                         \
            const int id = tid + i * 256;                                     \
            const int r = id >> 4, c4 = (id & 15) * 4;                        \
            const size_t go = base + (size_t)((kt) * 64 + r) * D_MODEL + c4;  \
            CP_ASYNC16(ks_b + ((buf) * KBUF + r * K_STRIDE + c4) * 4, K + go); \
            CP_ASYNC16(vs_b + ((buf) * VBUF + r * V_STRIDE + c4) * 4, V + go); \
        }                                                                     \
        CP_COMMIT();                                                          \
    } while (0)

    LOAD_KV(0, 0);
    LOAD_KV(1, 1);

    CP_WAIT(2);
    __syncthreads();

    float qf[8][4];
    {
        const int r0 = (wid * 16 + gid) * PS_STRIDE;
        const int r1 = (wid * 16 + gid + 8) * PS_STRIDE;
#pragma unroll
        for (int kc = 0; kc < 8; kc++) {
            const int c = kc * 8 + tig;
            qf[kc][0] = to_tf32(QSCALE * Ps[r0 + c]);
            qf[kc][1] = to_tf32(QSCALE * Ps[r1 + c]);
            qf[kc][2] = to_tf32(QSCALE * Ps[r0 + c + 4]);
            qf[kc][3] = to_tf32(QSCALE * Ps[r1 + c + 4]);
        }
    }
    __syncthreads();

    float o_acc[8][4];
#pragma unroll
    for (int nt = 0; nt < 8; nt++)
#pragma unroll
        for (int i = 0; i < 4; i++) o_acc[nt][i] = 0.0f;
    float m0r = -1e30f, m1r = -1e30f, l0r = 0.0f, l1r = 0.0f;

    float* Pw = Ps + wid * 16 * PS_STRIDE;
    const uint32_t pw_u = ps_b + (wid * 16 * PS_STRIDE + p_lm) * 4;

#pragma unroll 1
    for (int kt = 0; kt < 16; kt++) {
        if (kt < 15) { CP_WAIT(1); } else { CP_WAIT(0); }
        __syncthreads();
        const uint32_t ksc_u = ks_b + ((kt & 1) * KBUF + k_lm) * 4;
        const float* VsC = Vs + (kt & 1) * VBUF;

        float s[8][4];
#pragma unroll
        for (int nt = 0; nt < 8; nt++)
#pragma unroll
            for (int i = 0; i < 4; i++) s[nt][i] = 0.0f;

#pragma unroll
        for (int kc = 0; kc < 8; kc++) {
#pragma unroll
            for (int p = 0; p < 4; p++) {
                uint32_t r0, r1, r2, r3;
                LDMATRIX_X4(r0, r1, r2, r3,
                            ksc_u + (16 * p * K_STRIDE + kc * 8) * 4);
                mma_tf32(s[2 * p], qf[kc],
                         __uint_as_float(r0), __uint_as_float(r1));
                mma_tf32(s[2 * p + 1], qf[kc],
                         __uint_as_float(r2), __uint_as_float(r3));
            }
        }

        float mx0 = s[0][0], mx1 = s[0][2];
#pragma unroll
        for (int nt = 0; nt < 8; nt++) {
            mx0 = fmaxf(mx0, fmaxf(s[nt][0], s[nt][1]));
            mx1 = fmaxf(mx1, fmaxf(s[nt][2], s[nt][3]));
        }
        mx0 = fmaxf(mx0, __shfl_xor_sync(0xffffffffu, mx0, 1));
        mx0 = fmaxf(mx0, __shfl_xor_sync(0xffffffffu, mx0, 2));
        mx1 = fmaxf(mx1, __shfl_xor_sync(0xffffffffu, mx1, 1));
        mx1 = fmaxf(mx1, __shfl_xor_sync(0xffffffffu, mx1, 2));

        const float nm0 = fmaxf(m0r, mx0);
        const float nm1 = fmaxf(m1r, mx1);
        const float fac0 = exp2f(m0r - nm0);
        const float fac1 = exp2f(m1r - nm1);
        m0r = nm0; m1r = nm1;

        float sum0 = 0.0f, sum1 = 0.0f;
#pragma unroll
        for (int nt = 0; nt < 8; nt++) {
            s[nt][0] = exp2f(s[nt][0] - nm0);
            s[nt][1] = exp2f(s[nt][1] - nm0);
            s[nt][2] = exp2f(s[nt][2] - nm1);
            s[nt][3] = exp2f(s[nt][3] - nm1);
            sum0 += s[nt][0] + s[nt][1];
            sum1 += s[nt][2] + s[nt][3];
        }
        sum0 += __shfl_xor_sync(0xffffffffu, sum0, 1);
        sum0 += __shfl_xor_sync(0xffffffffu, sum0, 2);
        sum1 += __shfl_xor_sync(0xffffffffu, sum1, 1);
        sum1 += __shfl_xor_sync(0xffffffffu, sum1, 2);
        l0r = l0r * fac0 + sum0;
        l1r = l1r * fac1 + sum1;

#pragma unroll
        for (int nt = 0; nt < 8; nt++) {
            o_acc[nt][0] *= fac0; o_acc[nt][1] *= fac0;
            o_acc[nt][2] *= fac1; o_acc[nt][3] *= fac1;
        }

#pragma unroll
        for (int nt = 0; nt < 8; nt++) {
            const int c = nt * 8 + 2 * tig;
            *(float2*)&Pw[gid * PS_STRIDE + c] =
                make_float2(to_tf32(s[nt][0]), to_tf32(s[nt][1]));
            *(float2*)&Pw[(gid + 8) * PS_STRIDE + c] =
                make_float2(to_tf32(s[nt][2]), to_tf32(s[nt][3]));
        }
        __syncwarp();

#pragma unroll
        for (int kc = 0; kc < 8; kc++) {
            uint32_t a0, a1, a2, a3;
            LDMATRIX_X4(a0, a1, a2, a3, pw_u + kc * 32);
            float pa[4] = {__uint_as_float(a0), __uint_as_float(a1),
                           __uint_as_float(a2), __uint_as_float(a3)};
            float bv0[8], bv1[8];
            const int vr0 = (kc * 8 + tig) * V_STRIDE;
            const int vr1 = (kc * 8 + tig + 4) * V_STRIDE;
#pragma unroll
            for (int nt = 0; nt < 8; nt++) {
                bv0[nt] = VsC[vr0 + nt * 8 + gid];
                bv1[nt] = VsC[vr1 + nt * 8 + gid];
            }
#pragma unroll
            for (int nt = 0; nt < 8; nt++)
                mma_tf32(o_acc[nt], pa, bv0[nt], bv1[nt]);
        }

        __syncthreads();
        if (kt + 2 < 16) LOAD_KV(kt + 2, kt & 1);
    }

    const float inv0 = 1.0f / l0r;
    const float inv1 = 1.0f / l1r;
    const int r0 = q0 + wid * 16 + gid;
#pragma unroll
    for (int nt = 0; nt < 8; nt++) {
        const int c = nt * 8 + 2 * tig;
        *(float2*)&O[base + (size_t)r0 * D_MODEL + c] =
            make_float2(to_tf32(o_acc[nt][0] * inv0), to_tf32(o_acc[nt][1] * inv0));
        *(float2*)&O[base + (size_t)(r0 + 8) * D_MODEL + c] =
            make_float2(to_tf32(o_acc[nt][2] * inv1), to_tf32(o_acc[nt][3] * inv1));
    }
#undef LOAD_KV
}

// ---------------------------------------------------------------------------
extern "C" void kernel_launch(void* const* d_in, const int* in_sizes, int n_in,
                              void* d_out, int out_size) {
    (void)in_sizes; (void)n_in; (void)out_size;
    const float* x  = (const float*)d_in[0];
    const float* Wq = (const float*)d_in[1];
    const float* bq = (const float*)d_in[2];
    const float* Wk = (const float*)d_in[3];
    const float* bk = (const float*)d_in[4];
    const float* Wv = (const float*)d_in[5];
    const float* bv = (const float*)d_in[6];
    const float* Wo = (const float*)d_in[7];
    const float* bo = (const float*)d_in[8];
    float* out = (float*)d_out;

    float *q, *k, *v, *attn, *xr, *wqr, *wkr, *wvr, *wor;
    cudaGetSymbolAddress((void**)&q, g_q);
    cudaGetSymbolAddress((void**)&k, g_k);
    cudaGetSymbolAddress((void**)&v, g_v);
    cudaGetSymbolAddress((void**)&attn, g_attn);
    cudaGetSymbolAddress((void**)&xr, g_xr);
    cudaGetSymbolAddress((void**)&wqr, g_wqr);
    cudaGetSymbolAddress((void**)&wkr, g_wkr);
    cudaGetSymbolAddress((void**)&wvr, g_wvr);
    cudaGetSymbolAddress((void**)&wor, g_wor);

    const int smem_gemm = GSTG * (AS_SZ + BS_SZ) * (int)sizeof(float); // 107520
    cudaFuncSetAttribute(mma_gemm_kernel<0>,
                         cudaFuncAttributeMaxDynamicSharedMemorySize, smem_gemm);
    cudaFuncSetAttribute(mma_gemm_kernel<1>,
                         cudaFuncAttributeMaxDynamicSharedMemorySize, smem_gemm);
    const int smem_attn =
        (2 * KBUF + 2 * VBUF + 128 * PS_STRIDE) * (int)sizeof(float); // 110592
    cudaFuncSetAttribute(attention_kernel,
                         cudaFuncAttributeMaxDynamicSharedMemorySize, smem_attn);

    // ONE fused pre-rounding launch (x + 4 weights -> tf32)
    dim3 round_grid((XN4 + 255) / 256, 5);
    round_all_kernel<<<round_grid, 256>>>(x, xr, Wq, wqr, Wk, wkr, Wv, wvr, Wo, wor);

    // Fused QKV projection: one launch, blockIdx.z selects Q/K/V
    dim3 qkv_grid(D_MODEL / 128, TOK / 128, 3);   // (6, 64, 3)
    mma_gemm_kernel<1><<<qkv_grid, 256, smem_gemm>>>(
        xr, wqr, bq, q, wkr, bk, k, wvr, bv, v);

    // Tensor-core flash attention (2 CTAs/SM)
    dim3 attn_grid(SEQ / 128, BATCH * NH);        // (8, 96)
    attention_kernel<<<attn_grid, 256, smem_attn>>>(q, k, v, attn);

    // Output projection (full fp32 output)
    dim3 gemm_grid(D_MODEL / 128, TOK / 128);     // (6, 64)
    mma_gemm_kernel<0><<<gemm_grid, 256, smem_gemm>>>(
        attn, wor, bo, out, nullptr, nullptr, nullptr, nullptr, nullptr, nullptr);
}

// round 16
// speedup vs baseline: 1.9031x; 1.0094x over previous
#include <cuda_runtime.h>
#include <math.h>
#include <cstdint>

#define D_MODEL 768
#define NH      12
#define DHEAD   64
#define BATCH   8
#define SEQ     1024
#define TOK     (BATCH * SEQ)   // 8192

// Scratch (device globals — no runtime allocation allowed)
__device__ float g_q[TOK * D_MODEL];
__device__ float g_k[TOK * D_MODEL];
__device__ float g_v[TOK * D_MODEL];
__device__ float g_attn[TOK * D_MODEL];
__device__ float g_xr[TOK * D_MODEL];        // x rounded to tf32
__device__ float g_wqt[D_MODEL * D_MODEL];   // weights: transposed [n][k] + tf32
__device__ float g_wkt[D_MODEL * D_MODEL];
__device__ float g_wvt[D_MODEL * D_MODEL];
__device__ float g_wot[D_MODEL * D_MODEL];

__device__ __forceinline__ float to_tf32(float x) {
    float r;
    asm("cvt.rna.tf32.f32 %0, %1;" : "=f"(r) : "f"(x));
    return r;
}

__device__ __forceinline__ uint32_t smem_u32(const void* p) {
    uint32_t a;
    asm("{ .reg .u64 t; cvta.to.shared.u64 t, %1; cvt.u32.u64 %0, t; }"
        : "=r"(a) : "l"(p));
    return a;
}

// c += a @ b  (m16n8k8 tf32, fp32 accum)
__device__ __forceinline__ void mma_tf32(float* c, const float* a, float b0, float b1) {
    asm volatile(
        "mma.sync.aligned.m16n8k8.row.col.f32.tf32.tf32.f32 "
        "{%0,%1,%2,%3}, {%4,%5,%6,%7}, {%8,%9}, {%0,%1,%2,%3};"
        : "+f"(c[0]), "+f"(c[1]), "+f"(c[2]), "+f"(c[3])
        : "r"(__float_as_uint(a[0])), "r"(__float_as_uint(a[1])),
          "r"(__float_as_uint(a[2])), "r"(__float_as_uint(a[3])),
          "r"(__float_as_uint(b0)), "r"(__float_as_uint(b1)));
}

#define LDMATRIX_X4(r0, r1, r2, r3, addr)                                     \
    asm volatile("ldmatrix.sync.aligned.m8n8.x4.shared.b16 {%0,%1,%2,%3}, [%4];" \
                 : "=r"(r0), "=r"(r1), "=r"(r2), "=r"(r3) : "r"(addr))

#define CP_ASYNC16(saddr, gptr) \
    asm volatile("cp.async.cg.shared.global [%0], [%1], 16;" \
                 :: "r"(saddr), "l"(gptr) : "memory")
#define CP_COMMIT() asm volatile("cp.async.commit_group;" ::: "memory")
#define CP_WAIT(n)  asm volatile("cp.async.wait_group %0;" :: "n"(n) : "memory")

// ===========================================================================
// x pre-rounding to tf32 (float4)
// ===========================================================================
#define XN4 (TOK * D_MODEL / 4)        // 1572864

__global__ void __launch_bounds__(256)
round_x_kernel(const float* __restrict__ src, float* __restrict__ dst) {
    const int i = blockIdx.x * blockDim.x + threadIdx.x;
    if (i < XN4) {
        float4 v = ((const float4*)src)[i];
        v.x = to_tf32(v.x); v.y = to_tf32(v.y);
        v.z = to_tf32(v.z); v.w = to_tf32(v.w);
        ((float4*)dst)[i] = v;
    }
}

// ===========================================================================
// Weight transpose + tf32 round:  Wt[n][k] = tf32(W[k][n]).
// QKV weights are [H, D, DH]: n = h*64+dh -> src ((n>>6)*768 + k)*64 + (n&63)
// Wo is [K, N]:                            src k*768 + n
// 32x32 smem tiles, coalesced read + write. blockIdx.z picks the matrix.
// ===========================================================================
__global__ void __launch_bounds__(256)
wtrans_kernel(const float* __restrict__ wq, float* __restrict__ wqt,
              const float* __restrict__ wk, float* __restrict__ wkt,
              const float* __restrict__ wv, float* __restrict__ wvt,
              const float* __restrict__ wo, float* __restrict__ wot) {
    __shared__ float t[32][33];
    const int z = blockIdx.z;
    const float* src;
    float* dst;
    bool qkv = true;
    if (z == 0)      { src = wq; dst = wqt; }
    else if (z == 1) { src = wk; dst = wkt; }
    else if (z == 2) { src = wv; dst = wvt; }
    else             { src = wo; dst = wot; qkv = false; }

    const int k0 = blockIdx.x * 32;
    const int n0 = blockIdx.y * 32;
    const int tx = threadIdx.x & 31;
    const int ty = threadIdx.x >> 5;   // 0..7

#pragma unroll
    for (int j = 0; j < 4; j++) {
        const int k = k0 + ty + j * 8;
        const int n = n0 + tx;
        float v;
        if (qkv) v = src[((size_t)(n >> 6) * D_MODEL + k) * DHEAD + (n & 63)];
        else     v = src[(size_t)k * D_MODEL + n];
        t[ty + j * 8][tx] = to_tf32(v);
    }
    __syncthreads();
#pragma unroll
    for (int j = 0; j < 4; j++) {
        const int n = n0 + ty + j * 8;
        const int k = k0 + tx;
        dst[(size_t)n * D_MODEL + k] = t[tx][ty + j * 8];
    }
}

// ===========================================================================
// tf32 tensor-core GEMM + bias, v4.
// CTA tile 128x128, 256 threads = 8 warps (2 m-bands x 4 n-bands),
// warp tile 64x32. 3-stage cp.async pipeline, ONE barrier per iteration.
// B is PRE-TRANSPOSED [n][k] -> both A and B fragments via ldmatrix.x4
// (B-frag-from-[n][k] pattern validated by the attention QK^T path).
// QKV=1: fused Q/K/V (blockIdx.z selects), out rounded to tf32.
// QKV=0: single GEMM (Wo), full fp32 out.
// ===========================================================================
#define BK  32
#define NIT (D_MODEL / BK)   // 24
#define TS_STRIDE 36
#define TS_SZ (128 * TS_STRIDE)
#define GSTG 3

template <int QKV>
__global__ void __launch_bounds__(256, 2)
mma_gemm_kernel(const float* __restrict__ A,
                const float* __restrict__ B0, const float* __restrict__ bias0,
                float* __restrict__ C0,
                const float* __restrict__ B1, const float* __restrict__ bias1,
                float* __restrict__ C1,
                const float* __restrict__ B2, const float* __restrict__ bias2,
                float* __restrict__ C2) {
    extern __shared__ float gsm[];
    float* As_f = gsm;                    // [GSTG][128 m][36]
    float* Bs_f = gsm + GSTG * TS_SZ;     // [GSTG][128 n][36]

    const float* B    = B0;
    const float* bias = bias0;
    float*       C    = C0;
    if (QKV) {
        if (blockIdx.z == 1) { B = B1; bias = bias1; C = C1; }
        else if (blockIdx.z == 2) { B = B2; bias = bias2; C = C2; }
    }

    const int tid = threadIdx.x;
    const int lane = tid & 31;
    const int wid = tid >> 5;
    const int gid = lane >> 2;
    const int tig = lane & 3;
    const int warp_m = wid & 1;    // 2 bands x 64 rows
    const int warp_n = wid >> 1;   // 4 bands x 32 cols
    const int m0 = blockIdx.y * 128;
    const int n0 = blockIdx.x * 128;

    const uint32_t as_b = smem_u32(As_f);
    const uint32_t bs_b = smem_u32(Bs_f);

    // ldmatrix per-lane offsets (floats)
    const int a_lm = (lane & 15) * TS_STRIDE + (lane >> 4) * 4;
    const int b_lm = (((lane >> 4) & 1) * 8 + (lane & 7)) * TS_STRIDE
                   + ((lane >> 3) & 1) * 4;

    // Loaders: each tile 128 rows x 32 floats = 1024 float4, 4/thread.
    const int ld_col = (tid & 7) * 4;
    const float* aptr[4];
    const float* bptr[4];
    uint32_t a_dst[4], b_dst[4];
#pragma unroll
    for (int i = 0; i < 4; i++) {
        const int r = (tid + i * 256) >> 3;          // 0..127
        aptr[i] = A + (size_t)(m0 + r) * D_MODEL + ld_col;
        bptr[i] = B + (size_t)(n0 + r) * D_MODEL + ld_col;
        a_dst[i] = as_b + (r * TS_STRIDE + ld_col) * 4;
        b_dst[i] = bs_b + (r * TS_STRIDE + ld_col) * 4;
    }

#define LOAD_STAGE(koff, st)                                                  \
    do {                                                                      \
        _Pragma("unroll")                                                     \
        for (int i = 0; i < 4; i++)                                           \
            CP_ASYNC16(a_dst[i] + (st) * (TS_SZ * 4), aptr[i] + (koff));      \
        _Pragma("unroll")                                                     \
        for (int i = 0; i < 4; i++)                                           \
            CP_ASYNC16(b_dst[i] + (st) * (TS_SZ * 4), bptr[i] + (koff));      \
        CP_COMMIT();                                                          \
    } while (0)

    float acc[4][4][4];
#pragma unroll
    for (int mt = 0; mt < 4; mt++)
#pragma unroll
        for (int nt = 0; nt < 4; nt++)
#pragma unroll
            for (int i = 0; i < 4; i++) acc[mt][nt][i] = 0.0f;

    LOAD_STAGE(0, 0);
    LOAD_STAGE(BK, 1);

    int st = 0;
#pragma unroll 1
    for (int it = 0; it < NIT; it++) {
        CP_WAIT(1);
        __syncthreads();

        const int st2 = (st + 2 >= GSTG) ? st + 2 - GSTG : st + 2;
        if (it + 2 < NIT) {
            LOAD_STAGE((it + 2) * BK, st2);
        } else {
            CP_COMMIT();
        }

        const uint32_t asr_u = as_b + st * (TS_SZ * 4)
                             + (warp_m * 64 * TS_STRIDE + a_lm) * 4;
        const uint32_t bsr_u = bs_b + st * (TS_SZ * 4)
                             + (warp_n * 32 * TS_STRIDE + b_lm) * 4;

#pragma unroll
        for (int ks = 0; ks < 4; ks++) {
            const int kb = ks * 8;
            float a[4][4];
#pragma unroll
            for (int mt = 0; mt < 4; mt++) {
                uint32_t r0, r1, r2, r3;
                LDMATRIX_X4(r0, r1, r2, r3,
                            asr_u + (mt * 16 * TS_STRIDE + kb) * 4);
                a[mt][0] = __uint_as_float(r0);
                a[mt][1] = __uint_as_float(r1);
                a[mt][2] = __uint_as_float(r2);
                a[mt][3] = __uint_as_float(r3);
            }
            float b[4][2];
#pragma unroll
            for (int pr = 0; pr < 2; pr++) {
                uint32_t r0, r1, r2, r3;
                LDMATRIX_X4(r0, r1, r2, r3,
                            bsr_u + (pr * 16 * TS_STRIDE + kb) * 4);
                b[2 * pr][0]     = __uint_as_float(r0);
                b[2 * pr][1]     = __uint_as_float(r1);
                b[2 * pr + 1][0] = __uint_as_float(r2);
                b[2 * pr + 1][1] = __uint_as_float(r3);
            }
#pragma unroll
            for (int mt = 0; mt < 4; mt++)
#pragma unroll
                for (int nt = 0; nt < 4; nt++)
                    mma_tf32(acc[mt][nt], a[mt], b[nt][0], b[nt][1]);
        }

        st = (st + 1 >= GSTG) ? 0 : st + 1;
    }

    // ---- epilogue: fragment-direct stores + bias ----
#pragma unroll
    for (int nt = 0; nt < 4; nt++) {
        const int cn = n0 + warp_n * 32 + nt * 8 + 2 * tig;
        const float2 bb = *(const float2*)&bias[cn];
#pragma unroll
        for (int mt = 0; mt < 4; mt++) {
            const int r = m0 + warp_m * 64 + mt * 16 + gid;
            float2 v0 = make_float2(acc[mt][nt][0] + bb.x, acc[mt][nt][1] + bb.y);
            float2 v1 = make_float2(acc[mt][nt][2] + bb.x, acc[mt][nt][3] + bb.y);
            if (QKV) {
                v0.x = to_tf32(v0.x); v0.y = to_tf32(v0.y);
                v1.x = to_tf32(v1.x); v1.y = to_tf32(v1.y);
            }
            *(float2*)&C[(size_t)r * D_MODEL + cn] = v0;
            *(float2*)&C[(size_t)(r + 8) * D_MODEL + cn] = v1;
        }
    }
#undef LOAD_STAGE
}

// ===========================================================================
// Tensor-core flash attention (tf32 mma.sync) — v3 (UNCHANGED, passing):
//  * K B-fragments via ldmatrix.x4, P A-fragments via ldmatrix.x4
//  * softmax in base-2 (Q pre-scaled by 0.125*log2 e)
// ===========================================================================
#define K_STRIDE 68
#define V_STRIDE 72
#define PS_STRIDE 76
#define KBUF     (64 * K_STRIDE)
#define VBUF     (64 * V_STRIDE)
#define QSCALE   0.18033688011112042f   // 0.125 * log2(e)

__global__ void __launch_bounds__(256, 2)
attention_kernel(const float* __restrict__ Q, const float* __restrict__ K,
                 const float* __restrict__ V, float* __restrict__ O) {
    extern __shared__ float smem[];
    float* Ks = smem;                    // [2][64][K_STRIDE]
    float* Vs = Ks + 2 * KBUF;           // [2][64][V_STRIDE]
    float* Ps = Vs + 2 * VBUF;           // [128][PS_STRIDE]  (also Q staging)

    const int tid = threadIdx.x;
    const int lane = tid & 31;
    const int wid = tid >> 5;
    const int gid = lane >> 2;
    const int tig = lane & 3;
    const int b = blockIdx.y / NH;
    const int h = blockIdx.y % NH;
    const size_t base = (size_t)b * SEQ * D_MODEL + (size_t)h * DHEAD;
    const int q0 = blockIdx.x * 128;

    const uint32_t smem_b = smem_u32(smem);
    const uint32_t ks_b = smem_b;
    const uint32_t vs_b = smem_b + 2 * KBUF * 4;
    const uint32_t ps_b = smem_b + (2 * KBUF + 2 * VBUF) * 4;

    const int k_lm = (((lane >> 4) & 1) * 8 + (lane & 7)) * K_STRIDE
                   + ((lane >> 3) & 1) * 4;
    const int p_lm = ((lane & 7) + ((lane >> 3) & 1) * 8) * PS_STRIDE
                   + ((lane >> 4) & 1) * 4;

#pragma unroll
    for (int i = 0; i < 8; i++) {
        const int id = tid + i * 256;
        const int r = id >> 4, c4 = (id & 15) * 4;
        CP_ASYNC16(ps_b + (r * PS_STRIDE + c4) * 4,
                   Q + base + (size_t)(q0 + r) * D_MODEL + c4);
    }
    CP_COMMIT();

#define LOAD_KV(kt, buf)                                                      \
    do {                                                                      \
        _Pragma("unroll")                                                     \
        for (int i = 0; i < 4; i++) {                                         \
            const int id = tid + i * 256;                                     \
            const int r = id >> 4, c4 = (id & 15) * 4;                        \
            const size_t go = base + (size_t)((kt) * 64 + r) * D_MODEL + c4;  \
            CP_ASYNC16(ks_b + ((buf) * KBUF + r * K_STRIDE + c4) * 4, K + go); \
            CP_ASYNC16(vs_b + ((buf) * VBUF + r * V_STRIDE + c4) * 4, V + go); \
        }                                                                     \
        CP_COMMIT();                                                          \
    } while (0)

    LOAD_KV(0, 0);
    LOAD_KV(1, 1);

    CP_WAIT(2);
    __syncthreads();

    float qf[8][4];
    {
        const int r0 = (wid * 16 + gid) * PS_STRIDE;
        const int r1 = (wid * 16 + gid + 8) * PS_STRIDE;
#pragma unroll
        for (int kc = 0; kc < 8; kc++) {
            const int c = kc * 8 + tig;
            qf[kc][0] = to_tf32(QSCALE * Ps[r0 + c]);
            qf[kc][1] = to_tf32(QSCALE * Ps[r1 + c]);
            qf[kc][2] = to_tf32(QSCALE * Ps[r0 + c + 4]);
            qf[kc][3] = to_tf32(QSCALE * Ps[r1 + c + 4]);
        }
    }
    __syncthreads();

    float o_acc[8][4];
#pragma unroll
    for (int nt = 0; nt < 8; nt++)
#pragma unroll
        for (int i = 0; i < 4; i++) o_acc[nt][i] = 0.0f;
    float m0r = -1e30f, m1r = -1e30f, l0r = 0.0f, l1r = 0.0f;

    float* Pw = Ps + wid * 16 * PS_STRIDE;
    const uint32_t pw_u = ps_b + (wid * 16 * PS_STRIDE + p_lm) * 4;

#pragma unroll 1
    for (int kt = 0; kt < 16; kt++) {
        if (kt < 15) { CP_WAIT(1); } else { CP_WAIT(0); }
        __syncthreads();
        const uint32_t ksc_u = ks_b + ((kt & 1) * KBUF + k_lm) * 4;
        const float* VsC = Vs + (kt & 1) * VBUF;

        float s[8][4];
#pragma unroll
        for (int nt = 0; nt < 8; nt++)
#pragma unroll
            for (int i = 0; i < 4; i++) s[nt][i] = 0.0f;

#pragma unroll
        for (int kc = 0; kc < 8; kc++) {
#pragma unroll
            for (int p = 0; p < 4; p++) {
                uint32_t r0, r1, r2, r3;
                LDMATRIX_X4(r0, r1, r2, r3,
                            ksc_u + (16 * p * K_STRIDE + kc * 8) * 4);
                mma_tf32(s[2 * p], qf[kc],
                         __uint_as_float(r0), __uint_as_float(r1));
                mma_tf32(s[2 * p + 1], qf[kc],
                         __uint_as_float(r2), __uint_as_float(r3));
            }
        }

        float mx0 = s[0][0], mx1 = s[0][2];
#pragma unroll
        for (int nt = 0; nt < 8; nt++) {
            mx0 = fmaxf(mx0, fmaxf(s[nt][0], s[nt][1]));
            mx1 = fmaxf(mx1, fmaxf(s[nt][2], s[nt][3]));
        }
        mx0 = fmaxf(mx0, __shfl_xor_sync(0xffffffffu, mx0, 1));
        mx0 = fmaxf(mx0, __shfl_xor_sync(0xffffffffu, mx0, 2));
        mx1 = fmaxf(mx1, __shfl_xor_sync(0xffffffffu, mx1, 1));
        mx1 = fmaxf(mx1, __shfl_xor_sync(0xffffffffu, mx1, 2));

        const float nm0 = fmaxf(m0r, mx0);
        const float nm1 = fmaxf(m1r, mx1);
        const float fac0 = exp2f(m0r - nm0);
        const float fac1 = exp2f(m1r - nm1);
        m0r = nm0; m1r = nm1;

        float sum0 = 0.0f, sum1 = 0.0f;
#pragma unroll
        for (int nt = 0; nt < 8; nt++) {
            s[nt][0] = exp2f(s[nt][0] - nm0);
            s[nt][1] = exp2f(s[nt][1] - nm0);
            s[nt][2] = exp2f(s[nt][2] - nm1);
            s[nt][3] = exp2f(s[nt][3] - nm1);
            sum0 += s[nt][0] + s[nt][1];
            sum1 += s[nt][2] + s[nt][3];
        }
        sum0 += __shfl_xor_sync(0xffffffffu, sum0, 1);
        sum0 += __shfl_xor_sync(0xffffffffu, sum0, 2);
        sum1 += __shfl_xor_sync(0xffffffffu, sum1, 1);
        sum1 += __shfl_xor_sync(0xffffffffu, sum1, 2);
        l0r = l0r * fac0 + sum0;
        l1r = l1r * fac1 + sum1;

#pragma unroll
        for (int nt = 0; nt < 8; nt++) {
            o_acc[nt][0] *= fac0; o_acc[nt][1] *= fac0;
            o_acc[nt][2] *= fac1; o_acc[nt][3] *= fac1;
        }

#pragma unroll
        for (int nt = 0; nt < 8; nt++) {
            const int c = nt * 8 + 2 * tig;
            *(float2*)&Pw[gid * PS_STRIDE + c] =
                make_float2(to_tf32(s[nt][0]), to_tf32(s[nt][1]));
            *(float2*)&Pw[(gid + 8) * PS_STRIDE + c] =
                make_float2(to_tf32(s[nt][2]), to_tf32(s[nt][3]));
        }
        __syncwarp();

#pragma unroll
        for (int kc = 0; kc < 8; kc++) {
            uint32_t a0, a1, a2, a3;
            LDMATRIX_X4(a0, a1, a2, a3, pw_u + kc * 32);
            float pa[4] = {__uint_as_float(a0), __uint_as_float(a1),
                           __uint_as_float(a2), __uint_as_float(a3)};
            float bv0[8], bv1[8];
            const int vr0 = (kc * 8 + tig) * V_STRIDE;
            const int vr1 = (kc * 8 + tig + 4) * V_STRIDE;
#pragma unroll
            for (int nt = 0; nt < 8; nt++) {
                bv0[nt] = VsC[vr0 + nt * 8 + gid];
                bv1[nt] = VsC[vr1 + nt * 8 + gid];
            }
#pragma unroll
            for (int nt = 0; nt < 8; nt++)
                mma_tf32(o_acc[nt], pa, bv0[nt], bv1[nt]);
        }

        __syncthreads();
        if (kt + 2 < 16) LOAD_KV(kt + 2, kt & 1);
    }

    const float inv0 = 1.0f / l0r;
    const float inv1 = 1.0f / l1r;
    const int r0 = q0 + wid * 16 + gid;
#pragma unroll
    for (int nt = 0; nt < 8; nt++) {
        const int c = nt * 8 + 2 * tig;
        *(float2*)&O[base + (size_t)r0 * D_MODEL + c] =
            make_float2(to_tf32(o_acc[nt][0] * inv0), to_tf32(o_acc[nt][1] * inv0));
        *(float2*)&O[base + (size_t)(r0 + 8) * D_MODEL + c] =
            make_float2(to_tf32(o_acc[nt][2] * inv1), to_tf32(o_acc[nt][3] * inv1));
    }
#undef LOAD_KV
}

// ---------------------------------------------------------------------------
extern "C" void kernel_launch(void* const* d_in, const int* in_sizes, int n_in,
                              void* d_out, int out_size) {
    (void)in_sizes; (void)n_in; (void)out_size;
    const float* x  = (const float*)d_in[0];
    const float* Wq = (const float*)d_in[1];
    const float* bq = (const float*)d_in[2];
    const float* Wk = (const float*)d_in[3];
    const float* bk = (const float*)d_in[4];
    const float* Wv = (const float*)d_in[5];
    const float* bv = (const float*)d_in[6];
    const float* Wo = (const float*)d_in[7];
    const float* bo = (const float*)d_in[8];
    float* out = (float*)d_out;

    float *q, *k, *v, *attn, *xr, *wqt, *wkt, *wvt, *wot;
    cudaGetSymbolAddress((void**)&q, g_q);
    cudaGetSymbolAddress((void**)&k, g_k);
    cudaGetSymbolAddress((void**)&v, g_v);
    cudaGetSymbolAddress((void**)&attn, g_attn);
    cudaGetSymbolAddress((void**)&xr, g_xr);
    cudaGetSymbolAddress((void**)&wqt, g_wqt);
    cudaGetSymbolAddress((void**)&wkt, g_wkt);
    cudaGetSymbolAddress((void**)&wvt, g_wvt);
    cudaGetSymbolAddress((void**)&wot, g_wot);

    const int smem_gemm = GSTG * 2 * TS_SZ * (int)sizeof(float); // 110592
    cudaFuncSetAttribute(mma_gemm_kernel<0>,
                         cudaFuncAttributeMaxDynamicSharedMemorySize, smem_gemm);
    cudaFuncSetAttribute(mma_gemm_kernel<1>,
                         cudaFuncAttributeMaxDynamicSharedMemorySize, smem_gemm);
    const int smem_attn =
        (2 * KBUF + 2 * VBUF + 128 * PS_STRIDE) * (int)sizeof(float); // 110592
    cudaFuncSetAttribute(attention_kernel,
                         cudaFuncAttributeMaxDynamicSharedMemorySize, smem_attn);

    // Pre-round x; transpose+round all 4 weights to [n][k] tf32
    round_x_kernel<<<(XN4 + 255) / 256, 256>>>(x, xr);
    dim3 wt_grid(D_MODEL / 32, D_MODEL / 32, 4);   // (24, 24, 4)
    wtrans_kernel<<<wt_grid, 256>>>(Wq, wqt, Wk, wkt, Wv, wvt, Wo, wot);

    // Fused QKV projection: one launch, blockIdx.z selects Q/K/V
    dim3 qkv_grid(D_MODEL / 128, TOK / 128, 3);   // (6, 64, 3)
    mma_gemm_kernel<1><<<qkv_grid, 256, smem_gemm>>>(
        xr, wqt, bq, q, wkt, bk, k, wvt, bv, v);

    // Tensor-core flash attention (2 CTAs/SM)
    dim3 attn_grid(SEQ / 128, BATCH * NH);        // (8, 96)
    attention_kernel<<<attn_grid, 256, smem_attn>>>(q, k, v, attn);

    // Output projection (full fp32 output)
    dim3 gemm_grid(D_MODEL / 128, TOK / 128);     // (6, 64)
    mma_gemm_kernel<0><<<gemm_grid, 256, smem_gemm>>>(
        attn, wot, bo, out, nullptr, nullptr, nullptr, nullptr, nullptr, nullptr);
}